// round 1
// baseline (speedup 1.0000x reference)
#include <cuda_runtime.h>

#define NN   76800          // nodes (1024*75)
#define EE   1425408        // edges (1024*1392)
#define BB   1024           // graphs
#define S1C  36864          // clusters after pool1 (B*36)
#define S2C  25600          // clusters after pool2 (B*25)
#define NWORDS 42467328     // S1C*S1C/32 bits for dedup table

// ---------------- device scratch (static, no allocations) ----------------
__device__ float g_acc1[25*NN];
__device__ float g_x1[NN*32];
__device__ float g_deg1[NN];
__device__ int   g_cl1[NN];
__device__ unsigned g_px1[S1C*32];
__device__ float g_cnt1[S1C];
__device__ float g_psum1[S1C*2];
__device__ float g_ppos1[S1C*2];
__device__ float g_x2[S1C*32];
__device__ unsigned char g_kf1[EE];
__device__ float g_acc2[25*S1C*32];
__device__ float g_deg2[S1C];
__device__ float g_x2o[S1C*64];
__device__ int   g_cl2[S1C];
__device__ unsigned g_px2[S2C*64];
__device__ float g_cnt2[S2C];
__device__ float g_psum2[S2C*2];
__device__ float g_ppos2[S2C*2];
__device__ float g_x3[S2C*64];
__device__ unsigned char g_kf2[EE];
__device__ float g_acc3[25*S2C*64];
__device__ float g_deg3[S2C];
__device__ float g_x3o[S2C*64];
__device__ unsigned g_px3[BB*4*64];
__device__ float g_cnt3[BB*4];
__device__ unsigned g_amax[4];
__device__ unsigned g_bits[NWORDS];

// ---------------- helpers ----------------
__device__ __forceinline__ unsigned encf(float f){
    unsigned u=__float_as_uint(f);
    return (u&0x80000000u)? ~u : (u|0x80000000u);
}
__device__ __forceinline__ float decf(unsigned u){
    return (u&0x80000000u)? __uint_as_float(u&0x7FFFFFFFu) : __uint_as_float(~u);
}
__device__ __forceinline__ float eluf(float x){ return x>0.f ? x : expm1f(x); }

// ---------------- reset ----------------
__global__ void k_reset(){
    size_t i=(size_t)blockIdx.x*blockDim.x+threadIdx.x;
    size_t st=(size_t)gridDim.x*blockDim.x;
    float4 z=make_float4(0.f,0.f,0.f,0.f);
#define ZZ(ptr,n4) for(size_t j=i;j<(size_t)(n4);j+=st) ((float4*)(ptr))[j]=z;
    ZZ(g_acc1,  480000)
    ZZ(g_deg1,  19200)
    ZZ(g_px1,   294912)
    ZZ(g_cnt1,  9216)
    ZZ(g_psum1, 18432)
    ZZ(g_acc2,  7372800)
    ZZ(g_deg2,  9216)
    ZZ(g_px2,   409600)
    ZZ(g_cnt2,  6400)
    ZZ(g_psum2, 12800)
    ZZ(g_acc3,  10240000)
    ZZ(g_deg3,  6400)
    ZZ(g_px3,   65536)
    ZZ(g_cnt3,  1024)
#undef ZZ
    if(i==0){ g_amax[0]=0u; g_amax[1]=0u; g_amax[2]=0u; g_amax[3]=0u; }
}

// ---------------- stage 1: pseudo amax over raw positions ----------------
__global__ void k_amax0(const float* __restrict__ pos, const int* __restrict__ src,
                        const int* __restrict__ dst){
    int e=blockIdx.x*blockDim.x+threadIdx.x;
    unsigned cand=0u;
    if(e<EE){
        int s=src[e], d=dst[e];
        float c0=fabsf(pos[2*s]-pos[2*d]);
        float c1=fabsf(pos[2*s+1]-pos[2*d+1]);
        cand=__float_as_uint(fmaxf(c0,c1));
    }
    unsigned m=__reduce_max_sync(0xffffffffu,cand);
    if((threadIdx.x&31)==0 && m) atomicMax(&g_amax[0],m);
}

// ---------------- stage 1 scatter (Fin=1) ----------------
__global__ void k_scatter1(const float* __restrict__ x, const float* __restrict__ pos,
                           const int* __restrict__ src, const int* __restrict__ dst){
    int e=blockIdx.x*blockDim.x+threadIdx.x;
    if(e>=EE) return;
    int s=src[e], d=dst[e];
    float amax=fmaxf(__uint_as_float(g_amax[0]),1e-12f);
    float inv=0.5f/amax;
    float p0=(pos[2*s]-pos[2*d])*inv+0.5f;
    float p1=(pos[2*s+1]-pos[2*d+1])*inv+0.5f;
    float v0=fminf(fmaxf(p0,0.f),1.f)*4.f;
    float v1=fminf(fmaxf(p1,0.f),1.f)*4.f;
    float b0=fminf(floorf(v0),3.f), b1=fminf(floorf(v1),3.f);
    int i0=(int)b0, i1=(int)b1;
    float f0=v0-b0, f1=v1-b1;
    float xs=x[s];
    int k0=i0+5*i1;
    atomicAdd(&g_acc1[d*25+k0],   (1.f-f0)*(1.f-f1)*xs);
    atomicAdd(&g_acc1[d*25+k0+1], f0*(1.f-f1)*xs);
    atomicAdd(&g_acc1[d*25+k0+5], (1.f-f0)*f1*xs);
    atomicAdd(&g_acc1[d*25+k0+6], f0*f1*xs);
    atomicAdd(&g_deg1[d],1.f);
}

// ---------------- conv1 (Fin=1 -> 32) ----------------
__global__ void k_conv1(const float* __restrict__ x, const float* __restrict__ W1,
                        const float* __restrict__ r1, const float* __restrict__ b1){
    int idx=blockIdx.x*blockDim.x+threadIdx.x;
    if(idx>=NN*32) return;
    int n=idx>>5, o=idx&31;
    float s=0.f;
#pragma unroll
    for(int k=0;k<25;k++) s+=g_acc1[n*25+k]*W1[k*32+o];
    s=s/fmaxf(g_deg1[n],1.f)+x[n]*r1[o]+b1[o];
    g_x1[idx]=eluf(s);
}

// ---------------- pool1 (size=5, G=6) ----------------
__global__ void k_pool1(const float* __restrict__ pos){
    int idx=blockIdx.x*blockDim.x+threadIdx.x;
    if(idx>=NN*32) return;
    int n=idx>>5, f=idx&31;
    float px=pos[2*n], py=pos[2*n+1];
    int c0=min(max((int)floorf(px/5.f),0),5);
    int c1=min(max((int)floorf(py/5.f),0),5);
    int cl=(n/75)*36+c1*6+c0;
    atomicMax(&g_px1[cl*32+f], encf(g_x1[idx]));
    if(f==0){
        g_cl1[n]=cl;
        atomicAdd(&g_cnt1[cl],1.f);
        atomicAdd(&g_psum1[2*cl],px);
        atomicAdd(&g_psum1[2*cl+1],py);
    }
}

__global__ void k_fin1(){
    int idx=blockIdx.x*blockDim.x+threadIdx.x;
    if(idx>=S1C*32) return;
    int s=idx>>5, f=idx&31;
    float cnt=g_cnt1[s];
    g_x2[idx]=(cnt>0.f)? decf(g_px1[idx]) : 0.f;
    if(f<2) g_ppos1[2*s+f]=g_psum1[2*s+f]/fmaxf(cnt,1.f);
}

// ---------------- dedup pool1 edges ----------------
__global__ void k_clear1(const int* __restrict__ src, const int* __restrict__ dst){
    int e=blockIdx.x*blockDim.x+threadIdx.x;
    if(e>=EE) return;
    int a=g_cl1[src[e]], b=g_cl1[dst[e]];
    if(a!=b) g_bits[((unsigned)a*S1C+(unsigned)b)>>5]=0u;
}
__global__ void k_dedup1(const int* __restrict__ src, const int* __restrict__ dst){
    int e=blockIdx.x*blockDim.x+threadIdx.x;
    unsigned cand=0u;
    if(e<EE){
        unsigned char kf=0;
        int a=g_cl1[src[e]], b=g_cl1[dst[e]];
        if(a!=b){
            unsigned key=(unsigned)a*S1C+(unsigned)b;
            unsigned bit=1u<<(key&31u);
            if(!(atomicOr(&g_bits[key>>5],bit)&bit)){
                kf=1;
                float c0=fabsf(g_ppos1[2*a]-g_ppos1[2*b]);
                float c1=fabsf(g_ppos1[2*a+1]-g_ppos1[2*b+1]);
                cand=__float_as_uint(fmaxf(c0,c1));
            }
        }
        g_kf1[e]=kf;
    }
    unsigned m=__reduce_max_sync(0xffffffffu,cand);
    if((threadIdx.x&31)==0 && m) atomicMax(&g_amax[1],m);
}

// ---------------- stage 2 scatter (warp per edge, 32 feats) ----------------
__global__ void k_scatter2(const int* __restrict__ src, const int* __restrict__ dst){
    int t=blockIdx.x*blockDim.x+threadIdx.x;
    int e=t>>5, lane=t&31;
    if(e>=EE) return;
    if(!g_kf1[e]) return;
    int a=g_cl1[src[e]], b=g_cl1[dst[e]];
    float amax=fmaxf(__uint_as_float(g_amax[1]),1e-12f);
    float inv=0.5f/amax;
    float p0=(g_ppos1[2*a]-g_ppos1[2*b])*inv+0.5f;
    float p1=(g_ppos1[2*a+1]-g_ppos1[2*b+1])*inv+0.5f;
    float v0=fminf(fmaxf(p0,0.f),1.f)*4.f;
    float v1=fminf(fmaxf(p1,0.f),1.f)*4.f;
    float b0=fminf(floorf(v0),3.f), b1f=fminf(floorf(v1),3.f);
    int i0=(int)b0, i1=(int)b1f;
    float f0=v0-b0, f1=v1-b1f;
    float xs=g_x2[a*32+lane];
    int base=b*25+i0+5*i1;
    atomicAdd(&g_acc2[(base  )*32+lane], (1.f-f0)*(1.f-f1)*xs);
    atomicAdd(&g_acc2[(base+1)*32+lane], f0*(1.f-f1)*xs);
    atomicAdd(&g_acc2[(base+5)*32+lane], (1.f-f0)*f1*xs);
    atomicAdd(&g_acc2[(base+6)*32+lane], f0*f1*xs);
    if(lane==0) atomicAdd(&g_deg2[b],1.f);
}

// ---------------- tiled SGEMM conv: out = elu(A@W / deg + X@R + b) ----------------
// A: [M][KK], W: [KK][64], X: [M][FIN], R: [FIN][64]. 64x64 tile, 64 thr, 8x8/thr.
template<int KK,int FIN>
__global__ __launch_bounds__(64) void k_conv(
    const float* __restrict__ A, const float* __restrict__ Xin,
    const float* __restrict__ deg,
    const float* __restrict__ W, const float* __restrict__ R,
    const float* __restrict__ Bv, float* __restrict__ Out)
{
    __shared__ float As[16][64];
    __shared__ float Ws[16][64];
    int t=threadIdx.x;
    int n0=blockIdx.x*64;
    int tx=t&7, ty=t>>3;
    float c[8][8];
#pragma unroll
    for(int i=0;i<8;i++)
#pragma unroll
        for(int j=0;j<8;j++) c[i][j]=0.f;

    for(int phase=0;phase<2;phase++){
        const float* Ap = phase? Xin : A;
        const float* Wp = phase? R   : W;
        int kk  = phase? FIN : KK;
        int ldA = phase? FIN : KK;
        if(phase==1){
#pragma unroll
            for(int i=0;i<8;i++){
                float invd=1.f/fmaxf(deg[n0+ty*8+i],1.f);
#pragma unroll
                for(int j=0;j<8;j++) c[i][j]*=invd;
            }
        }
        for(int j0=0;j0<kk;j0+=16){
            __syncthreads();
            // A tile: thread t loads row (n0+t), 16 cols, stores transposed
            const float4* ar=(const float4*)(Ap+(size_t)(n0+t)*ldA+j0);
            float4 a0=ar[0],a1=ar[1],a2=ar[2],a3=ar[3];
            As[0][t]=a0.x;  As[1][t]=a0.y;  As[2][t]=a0.z;  As[3][t]=a0.w;
            As[4][t]=a1.x;  As[5][t]=a1.y;  As[6][t]=a1.z;  As[7][t]=a1.w;
            As[8][t]=a2.x;  As[9][t]=a2.y;  As[10][t]=a2.z; As[11][t]=a2.w;
            As[12][t]=a3.x; As[13][t]=a3.y; As[14][t]=a3.z; As[15][t]=a3.w;
            // W tile
#pragma unroll
            for(int q=0;q<4;q++){
                int p=t+64*q, wr=p>>4, wc=p&15;
                ((float4*)Ws[wr])[wc]=((const float4*)(Wp+(size_t)(j0+wr)*64))[wc];
            }
            __syncthreads();
#pragma unroll
            for(int k=0;k<16;k++){
                float4 xa=*(const float4*)&As[k][ty*8];
                float4 xb=*(const float4*)&As[k][ty*8+4];
                float4 wa=*(const float4*)&Ws[k][tx*8];
                float4 wb=*(const float4*)&Ws[k][tx*8+4];
                float av[8]={xa.x,xa.y,xa.z,xa.w,xb.x,xb.y,xb.z,xb.w};
                float wv[8]={wa.x,wa.y,wa.z,wa.w,wb.x,wb.y,wb.z,wb.w};
#pragma unroll
                for(int i=0;i<8;i++)
#pragma unroll
                    for(int j=0;j<8;j++) c[i][j]+=av[i]*wv[j];
            }
        }
    }
#pragma unroll
    for(int i=0;i<8;i++){
        int n=n0+ty*8+i;
#pragma unroll
        for(int j=0;j<8;j++){
            int o=tx*8+j;
            Out[(size_t)n*64+o]=eluf(c[i][j]+Bv[o]);
        }
    }
}

// ---------------- pool2 (size=7, G=5) over S1 clusters ----------------
__global__ void k_pool2(){
    int idx=blockIdx.x*blockDim.x+threadIdx.x;
    if(idx>=S1C*64) return;
    int n=idx>>6, f=idx&63;
    float qx=g_ppos1[2*n], qy=g_ppos1[2*n+1];
    int c0=min(max((int)floorf(qx/7.f),0),4);
    int c1=min(max((int)floorf(qy/7.f),0),4);
    int cl=(n/36)*25+c1*5+c0;
    if(f==0) g_cl2[n]=cl;
    if(g_cnt1[n]>0.f){
        atomicMax(&g_px2[cl*64+f], encf(g_x2o[idx]));
        if(f==0){
            atomicAdd(&g_cnt2[cl],1.f);
            atomicAdd(&g_psum2[2*cl],qx);
            atomicAdd(&g_psum2[2*cl+1],qy);
        }
    }
}
__global__ void k_fin2(){
    int idx=blockIdx.x*blockDim.x+threadIdx.x;
    if(idx>=S2C*64) return;
    int s=idx>>6, f=idx&63;
    float cnt=g_cnt2[s];
    g_x3[idx]=(cnt>0.f)? decf(g_px2[idx]) : 0.f;
    if(f<2) g_ppos2[2*s+f]=g_psum2[2*s+f]/fmaxf(cnt,1.f);
}

// ---------------- dedup pool2 edges ----------------
__global__ void k_clear2(const int* __restrict__ src, const int* __restrict__ dst){
    int e=blockIdx.x*blockDim.x+threadIdx.x;
    if(e>=EE) return;
    if(!g_kf1[e]) return;
    int a=g_cl2[g_cl1[src[e]]], b=g_cl2[g_cl1[dst[e]]];
    if(a!=b) g_bits[((unsigned)a*S2C+(unsigned)b)>>5]=0u;
}
__global__ void k_dedup2(const int* __restrict__ src, const int* __restrict__ dst){
    int e=blockIdx.x*blockDim.x+threadIdx.x;
    unsigned cand=0u;
    if(e<EE){
        unsigned char kf=0;
        if(g_kf1[e]){
            int a=g_cl2[g_cl1[src[e]]], b=g_cl2[g_cl1[dst[e]]];
            if(a!=b){
                unsigned key=(unsigned)a*S2C+(unsigned)b;
                unsigned bit=1u<<(key&31u);
                if(!(atomicOr(&g_bits[key>>5],bit)&bit)){
                    kf=1;
                    float c0=fabsf(g_ppos2[2*a]-g_ppos2[2*b]);
                    float c1=fabsf(g_ppos2[2*a+1]-g_ppos2[2*b+1]);
                    cand=__float_as_uint(fmaxf(c0,c1));
                }
            }
        }
        g_kf2[e]=kf;
    }
    unsigned m=__reduce_max_sync(0xffffffffu,cand);
    if((threadIdx.x&31)==0 && m) atomicMax(&g_amax[2],m);
}

// ---------------- stage 3 scatter (warp per edge, 64 feats) ----------------
__global__ void k_scatter3(const int* __restrict__ src, const int* __restrict__ dst){
    int t=blockIdx.x*blockDim.x+threadIdx.x;
    int e=t>>5, lane=t&31;
    if(e>=EE) return;
    if(!g_kf2[e]) return;
    int a=g_cl2[g_cl1[src[e]]], b=g_cl2[g_cl1[dst[e]]];
    float amax=fmaxf(__uint_as_float(g_amax[2]),1e-12f);
    float inv=0.5f/amax;
    float p0=(g_ppos2[2*a]-g_ppos2[2*b])*inv+0.5f;
    float p1=(g_ppos2[2*a+1]-g_ppos2[2*b+1])*inv+0.5f;
    float v0=fminf(fmaxf(p0,0.f),1.f)*4.f;
    float v1=fminf(fmaxf(p1,0.f),1.f)*4.f;
    float b0=fminf(floorf(v0),3.f), b1f=fminf(floorf(v1),3.f);
    int i0=(int)b0, i1=(int)b1f;
    float f0=v0-b0, f1=v1-b1f;
    float x0=g_x3[a*64+lane], x1=g_x3[a*64+32+lane];
    int base=b*25+i0+5*i1;
    float wA=(1.f-f0)*(1.f-f1), wB=f0*(1.f-f1), wC=(1.f-f0)*f1, wD=f0*f1;
    atomicAdd(&g_acc3[(base  )*64+lane],    wA*x0);
    atomicAdd(&g_acc3[(base  )*64+32+lane], wA*x1);
    atomicAdd(&g_acc3[(base+1)*64+lane],    wB*x0);
    atomicAdd(&g_acc3[(base+1)*64+32+lane], wB*x1);
    atomicAdd(&g_acc3[(base+5)*64+lane],    wC*x0);
    atomicAdd(&g_acc3[(base+5)*64+32+lane], wC*x1);
    atomicAdd(&g_acc3[(base+6)*64+lane],    wD*x0);
    atomicAdd(&g_acc3[(base+6)*64+32+lane], wD*x1);
    if(lane==0) atomicAdd(&g_deg3[b],1.f);
}

// ---------------- final 2x2 pool ----------------
__global__ void k_fpool(){
    int idx=blockIdx.x*blockDim.x+threadIdx.x;
    if(idx>=S2C*64) return;
    int n=idx>>6, f=idx&63;
    if(g_cnt2[n]<=0.f) return;
    float qx=g_ppos2[2*n], qy=g_ppos2[2*n+1];
    int c0=min(max((int)floorf(qx/14.f),0),1);
    int c1=min(max((int)floorf(qy/14.f),0),1);
    int cl=(n/25)*4+c1*2+c0;
    atomicMax(&g_px3[cl*64+f], encf(g_x3o[idx]));
    if(f==0) atomicAdd(&g_cnt3[cl],1.f);
}

// ---------------- head: FC(256->128) + elu + FC(128->10) + log_softmax ----------------
__global__ void k_head(const float* __restrict__ fw1, const float* __restrict__ fb1,
                       const float* __restrict__ fw2, const float* __restrict__ fb2,
                       float* __restrict__ out){
    __shared__ float in[256];
    __shared__ float h[128];
    __shared__ float lg[10];
    __shared__ float lse;
    int b=blockIdx.x, t=threadIdx.x;
    for(int i=t;i<256;i+=128){
        int q=i>>6, f=i&63;
        int cl=b*4+q;
        in[i]=(g_cnt3[cl]>0.f)? decf(g_px3[cl*64+f]) : 0.f;
    }
    __syncthreads();
    float s=fb1[t];
    for(int i=0;i<256;i++) s+=in[i]*fw1[t*256+i];
    h[t]=eluf(s);
    __syncthreads();
    if(t<10){
        float l=fb2[t];
        for(int i=0;i<128;i++) l+=h[i]*fw2[t*128+i];
        lg[t]=l;
    }
    __syncthreads();
    if(t==0){
        float m=lg[0];
        for(int i=1;i<10;i++) m=fmaxf(m,lg[i]);
        float ss=0.f;
        for(int i=0;i<10;i++) ss+=expf(lg[i]-m);
        lse=m+logf(ss);
    }
    __syncthreads();
    if(t<10) out[b*10+t]=lg[t]-lse;
}

// ---------------- launch ----------------
extern "C" void kernel_launch(void* const* d_in, const int* in_sizes, int n_in,
                              void* d_out, int out_size){
    const float* x   =(const float*)d_in[0];
    const float* pos =(const float*)d_in[1];
    const int*   src =(const int*)  d_in[2];
    const int*   dst =(const int*)  d_in[3];
    const float* W1  =(const float*)d_in[4];
    const float* r1  =(const float*)d_in[5];
    const float* b1  =(const float*)d_in[6];
    const float* W2  =(const float*)d_in[7];
    const float* r2  =(const float*)d_in[8];
    const float* b2  =(const float*)d_in[9];
    const float* W3  =(const float*)d_in[10];
    const float* r3  =(const float*)d_in[11];
    const float* b3  =(const float*)d_in[12];
    const float* fw1 =(const float*)d_in[13];
    const float* fb1 =(const float*)d_in[14];
    const float* fw2 =(const float*)d_in[15];
    const float* fb2 =(const float*)d_in[16];
    float* out=(float*)d_out;

    float *pA2,*pX2,*pD2,*pX2o,*pA3,*pX3,*pD3,*pX3o;
    cudaGetSymbolAddress((void**)&pA2,  g_acc2);
    cudaGetSymbolAddress((void**)&pX2,  g_x2);
    cudaGetSymbolAddress((void**)&pD2,  g_deg2);
    cudaGetSymbolAddress((void**)&pX2o, g_x2o);
    cudaGetSymbolAddress((void**)&pA3,  g_acc3);
    cudaGetSymbolAddress((void**)&pX3,  g_x3);
    cudaGetSymbolAddress((void**)&pD3,  g_deg3);
    cudaGetSymbolAddress((void**)&pX3o, g_x3o);

    k_reset<<<2048,256>>>();
    k_amax0<<<EE/256,256>>>(pos,src,dst);
    k_scatter1<<<EE/256,256>>>(x,pos,src,dst);
    k_conv1<<<(NN*32)/256,256>>>(x,W1,r1,b1);
    k_pool1<<<(NN*32)/256,256>>>(pos);
    k_fin1<<<(S1C*32)/256,256>>>();
    k_clear1<<<EE/256,256>>>(src,dst);
    k_dedup1<<<EE/256,256>>>(src,dst);
    k_scatter2<<<EE/8,256>>>(src,dst);
    k_conv<800,32><<<S1C/64,64>>>(pA2,pX2,pD2,W2,r2,b2,pX2o);
    k_pool2<<<(S1C*64)/256,256>>>();
    k_fin2<<<(S2C*64)/256,256>>>();
    k_clear2<<<EE/256,256>>>(src,dst);
    k_dedup2<<<EE/256,256>>>(src,dst);
    k_scatter3<<<EE/8,256>>>(src,dst);
    k_conv<1600,64><<<S2C/64,64>>>(pA3,pX3,pD3,W3,r3,b3,pX3o);
    k_fpool<<<(S2C*64)/256,256>>>();
    k_head<<<BB,128>>>(fw1,fb1,fw2,fb2,out);
}

// round 2
// speedup vs baseline: 1.1227x; 1.1227x over previous
#include <cuda_runtime.h>

#define NN   76800          // nodes (1024*75)
#define EE   1425408        // edges (1024*1392)
#define BB   1024           // graphs
#define S1C  36864          // clusters after pool1 (B*36)
#define S2C  25600          // clusters after pool2 (B*25)
#define NWORDS 42467328     // S1C*S1C/32 bits for dedup table

// ---------------- device scratch (static, no allocations) ----------------
__device__ float g_acc1[25*NN];
__device__ float g_x1[NN*32];
__device__ float g_deg1[NN];
__device__ int   g_cl1[NN];
__device__ unsigned g_px1[S1C*32];
__device__ float g_cnt1[S1C];
__device__ float g_psum1[S1C*2];
__device__ float g_ppos1[S1C*2];
__device__ float g_x2[S1C*32];
__device__ unsigned char g_kf1[EE];
__device__ float g_acc2[25*S1C*32];
__device__ float g_deg2[S1C];
__device__ float g_x2o[S1C*64];
__device__ int   g_cl2[S1C];
__device__ unsigned g_px2[S2C*64];
__device__ float g_cnt2[S2C];
__device__ float g_psum2[S2C*2];
__device__ float g_ppos2[S2C*2];
__device__ float g_x3[S2C*64];
__device__ unsigned char g_kf2[EE];
__device__ float g_acc3[25*S2C*64];
__device__ float g_deg3[S2C];
__device__ float g_x3o[S2C*64];
__device__ unsigned g_px3[BB*4*64];
__device__ float g_cnt3[BB*4];
__device__ unsigned g_amax[4];
__device__ unsigned g_bits[NWORDS];

// ---------------- helpers ----------------
__device__ __forceinline__ unsigned encf(float f){
    unsigned u=__float_as_uint(f);
    return (u&0x80000000u)? ~u : (u|0x80000000u);
}
__device__ __forceinline__ float decf(unsigned u){
    return (u&0x80000000u)? __uint_as_float(u&0x7FFFFFFFu) : __uint_as_float(~u);
}
__device__ __forceinline__ float eluf(float x){ return x>0.f ? x : expm1f(x); }

__device__ __forceinline__ void redAddF(float* p, float v){
    asm volatile("red.global.add.f32 [%0], %1;" :: "l"(p), "f"(v) : "memory");
}
__device__ __forceinline__ void redAdd2(float* p, float a, float b){
    asm volatile("red.global.add.v2.f32 [%0], {%1, %2};" :: "l"(p), "f"(a), "f"(b) : "memory");
}
__device__ __forceinline__ void redMaxU(unsigned* p, unsigned v){
    asm volatile("red.global.max.u32 [%0], %1;" :: "l"(p), "r"(v) : "memory");
}

// ---------------- reset ----------------
__global__ void k_reset(){
    size_t i=(size_t)blockIdx.x*blockDim.x+threadIdx.x;
    size_t st=(size_t)gridDim.x*blockDim.x;
    float4 z=make_float4(0.f,0.f,0.f,0.f);
#define ZZ(ptr,n4) for(size_t j=i;j<(size_t)(n4);j+=st) ((float4*)(ptr))[j]=z;
    ZZ(g_acc1,  480000)
    ZZ(g_deg1,  19200)
    ZZ(g_px1,   294912)
    ZZ(g_cnt1,  9216)
    ZZ(g_psum1, 18432)
    ZZ(g_acc2,  7372800)
    ZZ(g_deg2,  9216)
    ZZ(g_px2,   409600)
    ZZ(g_cnt2,  6400)
    ZZ(g_psum2, 12800)
    ZZ(g_acc3,  10240000)
    ZZ(g_deg3,  6400)
    ZZ(g_px3,   65536)
    ZZ(g_cnt3,  1024)
#undef ZZ
    if(i==0){ g_amax[0]=0u; g_amax[1]=0u; g_amax[2]=0u; g_amax[3]=0u; }
}

// ---------------- stage 1: pseudo amax over raw positions ----------------
__global__ void k_amax0(const float* __restrict__ pos, const int* __restrict__ src,
                        const int* __restrict__ dst){
    int e=blockIdx.x*blockDim.x+threadIdx.x;
    unsigned cand=0u;
    if(e<EE){
        int s=src[e], d=dst[e];
        float c0=fabsf(pos[2*s]-pos[2*d]);
        float c1=fabsf(pos[2*s+1]-pos[2*d+1]);
        cand=__float_as_uint(fmaxf(c0,c1));
    }
    unsigned m=__reduce_max_sync(0xffffffffu,cand);
    if((threadIdx.x&31)==0 && m) redMaxU(&g_amax[0],m);
}

// ---------------- stage 1 scatter (Fin=1) ----------------
__global__ void k_scatter1(const float* __restrict__ x, const float* __restrict__ pos,
                           const int* __restrict__ src, const int* __restrict__ dst){
    int e=blockIdx.x*blockDim.x+threadIdx.x;
    if(e>=EE) return;
    int s=src[e], d=dst[e];
    float amax=fmaxf(__uint_as_float(g_amax[0]),1e-12f);
    float inv=0.5f/amax;
    float p0=(pos[2*s]-pos[2*d])*inv+0.5f;
    float p1=(pos[2*s+1]-pos[2*d+1])*inv+0.5f;
    float v0=fminf(fmaxf(p0,0.f),1.f)*4.f;
    float v1=fminf(fmaxf(p1,0.f),1.f)*4.f;
    float b0=fminf(floorf(v0),3.f), b1=fminf(floorf(v1),3.f);
    int i0=(int)b0, i1=(int)b1;
    float f0=v0-b0, f1=v1-b1;
    float xs=x[s];
    int k0=i0+5*i1;
    redAddF(&g_acc1[d*25+k0],   (1.f-f0)*(1.f-f1)*xs);
    redAddF(&g_acc1[d*25+k0+1], f0*(1.f-f1)*xs);
    redAddF(&g_acc1[d*25+k0+5], (1.f-f0)*f1*xs);
    redAddF(&g_acc1[d*25+k0+6], f0*f1*xs);
    redAddF(&g_deg1[d],1.f);
}

// ---------------- conv1 (Fin=1 -> 32) ----------------
__global__ void k_conv1(const float* __restrict__ x, const float* __restrict__ W1,
                        const float* __restrict__ r1, const float* __restrict__ b1){
    int idx=blockIdx.x*blockDim.x+threadIdx.x;
    if(idx>=NN*32) return;
    int n=idx>>5, o=idx&31;
    float s=0.f;
#pragma unroll
    for(int k=0;k<25;k++) s+=g_acc1[n*25+k]*W1[k*32+o];
    s=s/fmaxf(g_deg1[n],1.f)+x[n]*r1[o]+b1[o];
    g_x1[idx]=eluf(s);
}

// ---------------- pool1 (size=5, G=6) ----------------
__global__ void k_pool1(const float* __restrict__ pos){
    int idx=blockIdx.x*blockDim.x+threadIdx.x;
    if(idx>=NN*32) return;
    int n=idx>>5, f=idx&31;
    float px=pos[2*n], py=pos[2*n+1];
    int c0=min(max((int)floorf(px/5.f),0),5);
    int c1=min(max((int)floorf(py/5.f),0),5);
    int cl=(n/75)*36+c1*6+c0;
    redMaxU(&g_px1[cl*32+f], encf(g_x1[idx]));
    if(f==0){
        g_cl1[n]=cl;
        redAddF(&g_cnt1[cl],1.f);
        redAdd2(&g_psum1[2*cl],px,py);
    }
}

__global__ void k_fin1(){
    int idx=blockIdx.x*blockDim.x+threadIdx.x;
    if(idx>=S1C*32) return;
    int s=idx>>5, f=idx&31;
    float cnt=g_cnt1[s];
    g_x2[idx]=(cnt>0.f)? decf(g_px1[idx]) : 0.f;
    if(f<2) g_ppos1[2*s+f]=g_psum1[2*s+f]/fmaxf(cnt,1.f);
}

// ---------------- dedup pool1 edges ----------------
__global__ void k_clear1(const int* __restrict__ src, const int* __restrict__ dst){
    int e=blockIdx.x*blockDim.x+threadIdx.x;
    if(e>=EE) return;
    int a=g_cl1[src[e]], b=g_cl1[dst[e]];
    if(a!=b) g_bits[((unsigned)a*S1C+(unsigned)b)>>5]=0u;
}
__global__ void k_dedup1(const int* __restrict__ src, const int* __restrict__ dst){
    int e=blockIdx.x*blockDim.x+threadIdx.x;
    unsigned cand=0u;
    if(e<EE){
        unsigned char kf=0;
        int a=g_cl1[src[e]], b=g_cl1[dst[e]];
        if(a!=b){
            unsigned key=(unsigned)a*S1C+(unsigned)b;
            unsigned bit=1u<<(key&31u);
            if(!(atomicOr(&g_bits[key>>5],bit)&bit)){
                kf=1;
                float c0=fabsf(g_ppos1[2*a]-g_ppos1[2*b]);
                float c1=fabsf(g_ppos1[2*a+1]-g_ppos1[2*b+1]);
                cand=__float_as_uint(fmaxf(c0,c1));
            }
        }
        g_kf1[e]=kf;
    }
    unsigned m=__reduce_max_sync(0xffffffffu,cand);
    if((threadIdx.x&31)==0 && m) redMaxU(&g_amax[1],m);
}

// ---------------- stage 2 scatter: 16 threads/edge, float2 per lane ----------------
__global__ void k_scatter2(const int* __restrict__ src, const int* __restrict__ dst){
    int t=blockIdx.x*blockDim.x+threadIdx.x;
    int e=t>>4, sub=t&15;
    if(e>=EE) return;
    if(!g_kf1[e]) return;
    int a=g_cl1[src[e]], b=g_cl1[dst[e]];
    float amax=fmaxf(__uint_as_float(g_amax[1]),1e-12f);
    float inv=0.5f/amax;
    float p0=(g_ppos1[2*a]-g_ppos1[2*b])*inv+0.5f;
    float p1=(g_ppos1[2*a+1]-g_ppos1[2*b+1])*inv+0.5f;
    float v0=fminf(fmaxf(p0,0.f),1.f)*4.f;
    float v1=fminf(fmaxf(p1,0.f),1.f)*4.f;
    float b0=fminf(floorf(v0),3.f), b1f=fminf(floorf(v1),3.f);
    int i0=(int)b0, i1=(int)b1f;
    float f0=v0-b0, f1=v1-b1f;
    float2 xs=*(const float2*)&g_x2[a*32+2*sub];
    int base=b*25+i0+5*i1;
    float wA=(1.f-f0)*(1.f-f1), wB=f0*(1.f-f1), wC=(1.f-f0)*f1, wD=f0*f1;
    redAdd2(&g_acc2[(base  )*32+2*sub], wA*xs.x, wA*xs.y);
    redAdd2(&g_acc2[(base+1)*32+2*sub], wB*xs.x, wB*xs.y);
    redAdd2(&g_acc2[(base+5)*32+2*sub], wC*xs.x, wC*xs.y);
    redAdd2(&g_acc2[(base+6)*32+2*sub], wD*xs.x, wD*xs.y);
    if(sub==0) redAddF(&g_deg2[b],1.f);
}

// ---------------- tiled SGEMM conv: out = elu(A@W / deg + X@R + b) ----------------
// 64x64 tile, BK=16, 256 threads, 4x4 per thread.
template<int KK,int FIN>
__global__ __launch_bounds__(256) void k_conv(
    const float* __restrict__ A, const float* __restrict__ Xin,
    const float* __restrict__ deg,
    const float* __restrict__ W, const float* __restrict__ R,
    const float* __restrict__ Bv, float* __restrict__ Out)
{
    __shared__ float As[16][65];
    __shared__ float Ws[16][64];
    int t=threadIdx.x;
    int n0=blockIdx.x*64;
    int tx=t&15, ty=t>>4;          // tx: col quad, ty: row quad
    int lr=t>>2, lc=(t&3)*4;       // A-load: row, col-base
    float c[4][4];
#pragma unroll
    for(int i=0;i<4;i++)
#pragma unroll
        for(int j=0;j<4;j++) c[i][j]=0.f;

    for(int phase=0;phase<2;phase++){
        const float* Ap = phase? Xin : A;
        const float* Wp = phase? R   : W;
        int kk  = phase? FIN : KK;
        int ldA = phase? FIN : KK;
        if(phase==1){
#pragma unroll
            for(int i=0;i<4;i++){
                float invd=1.f/fmaxf(deg[n0+ty*4+i],1.f);
#pragma unroll
                for(int j=0;j<4;j++) c[i][j]*=invd;
            }
        }
        for(int j0=0;j0<kk;j0+=16){
            __syncthreads();
            float4 av=*(const float4*)(Ap+(size_t)(n0+lr)*ldA+j0+lc);
            As[lc+0][lr]=av.x; As[lc+1][lr]=av.y; As[lc+2][lr]=av.z; As[lc+3][lr]=av.w;
            *(float4*)&Ws[ty][tx*4]=*(const float4*)(Wp+(size_t)(j0+ty)*64+tx*4);
            __syncthreads();
#pragma unroll
            for(int k=0;k<16;k++){
                float a0=As[k][ty*4+0], a1=As[k][ty*4+1], a2=As[k][ty*4+2], a3=As[k][ty*4+3];
                float4 w=*(const float4*)&Ws[k][tx*4];
                c[0][0]+=a0*w.x; c[0][1]+=a0*w.y; c[0][2]+=a0*w.z; c[0][3]+=a0*w.w;
                c[1][0]+=a1*w.x; c[1][1]+=a1*w.y; c[1][2]+=a1*w.z; c[1][3]+=a1*w.w;
                c[2][0]+=a2*w.x; c[2][1]+=a2*w.y; c[2][2]+=a2*w.z; c[2][3]+=a2*w.w;
                c[3][0]+=a3*w.x; c[3][1]+=a3*w.y; c[3][2]+=a3*w.z; c[3][3]+=a3*w.w;
            }
        }
    }
    float4 bv=*(const float4*)&Bv[tx*4];
#pragma unroll
    for(int i=0;i<4;i++){
        int n=n0+ty*4+i;
        float4 o;
        o.x=eluf(c[i][0]+bv.x); o.y=eluf(c[i][1]+bv.y);
        o.z=eluf(c[i][2]+bv.z); o.w=eluf(c[i][3]+bv.w);
        *(float4*)&Out[(size_t)n*64+tx*4]=o;
    }
}

// ---------------- pool2 (size=7, G=5) over S1 clusters ----------------
__global__ void k_pool2(){
    int idx=blockIdx.x*blockDim.x+threadIdx.x;
    if(idx>=S1C*64) return;
    int n=idx>>6, f=idx&63;
    float qx=g_ppos1[2*n], qy=g_ppos1[2*n+1];
    int c0=min(max((int)floorf(qx/7.f),0),4);
    int c1=min(max((int)floorf(qy/7.f),0),4);
    int cl=(n/36)*25+c1*5+c0;
    if(f==0) g_cl2[n]=cl;
    if(g_cnt1[n]>0.f){
        redMaxU(&g_px2[cl*64+f], encf(g_x2o[idx]));
        if(f==0){
            redAddF(&g_cnt2[cl],1.f);
            redAdd2(&g_psum2[2*cl],qx,qy);
        }
    }
}
__global__ void k_fin2(){
    int idx=blockIdx.x*blockDim.x+threadIdx.x;
    if(idx>=S2C*64) return;
    int s=idx>>6, f=idx&63;
    float cnt=g_cnt2[s];
    g_x3[idx]=(cnt>0.f)? decf(g_px2[idx]) : 0.f;
    if(f<2) g_ppos2[2*s+f]=g_psum2[2*s+f]/fmaxf(cnt,1.f);
}

// ---------------- dedup pool2 edges ----------------
__global__ void k_clear2(const int* __restrict__ src, const int* __restrict__ dst){
    int e=blockIdx.x*blockDim.x+threadIdx.x;
    if(e>=EE) return;
    if(!g_kf1[e]) return;
    int a=g_cl2[g_cl1[src[e]]], b=g_cl2[g_cl1[dst[e]]];
    if(a!=b) g_bits[((unsigned)a*S2C+(unsigned)b)>>5]=0u;
}
__global__ void k_dedup2(const int* __restrict__ src, const int* __restrict__ dst){
    int e=blockIdx.x*blockDim.x+threadIdx.x;
    unsigned cand=0u;
    if(e<EE){
        unsigned char kf=0;
        if(g_kf1[e]){
            int a=g_cl2[g_cl1[src[e]]], b=g_cl2[g_cl1[dst[e]]];
            if(a!=b){
                unsigned key=(unsigned)a*S2C+(unsigned)b;
                unsigned bit=1u<<(key&31u);
                if(!(atomicOr(&g_bits[key>>5],bit)&bit)){
                    kf=1;
                    float c0=fabsf(g_ppos2[2*a]-g_ppos2[2*b]);
                    float c1=fabsf(g_ppos2[2*a+1]-g_ppos2[2*b+1]);
                    cand=__float_as_uint(fmaxf(c0,c1));
                }
            }
        }
        g_kf2[e]=kf;
    }
    unsigned m=__reduce_max_sync(0xffffffffu,cand);
    if((threadIdx.x&31)==0 && m) redMaxU(&g_amax[2],m);
}

// ---------------- stage 3 scatter: warp per edge, float2 per lane ----------------
__global__ void k_scatter3(const int* __restrict__ src, const int* __restrict__ dst){
    int t=blockIdx.x*blockDim.x+threadIdx.x;
    int e=t>>5, lane=t&31;
    if(e>=EE) return;
    if(!g_kf2[e]) return;
    int a=g_cl2[g_cl1[src[e]]], b=g_cl2[g_cl1[dst[e]]];
    float amax=fmaxf(__uint_as_float(g_amax[2]),1e-12f);
    float inv=0.5f/amax;
    float p0=(g_ppos2[2*a]-g_ppos2[2*b])*inv+0.5f;
    float p1=(g_ppos2[2*a+1]-g_ppos2[2*b+1])*inv+0.5f;
    float v0=fminf(fmaxf(p0,0.f),1.f)*4.f;
    float v1=fminf(fmaxf(p1,0.f),1.f)*4.f;
    float b0=fminf(floorf(v0),3.f), b1f=fminf(floorf(v1),3.f);
    int i0=(int)b0, i1=(int)b1f;
    float f0=v0-b0, f1=v1-b1f;
    float2 xs=*(const float2*)&g_x3[a*64+2*lane];
    int base=b*25+i0+5*i1;
    float wA=(1.f-f0)*(1.f-f1), wB=f0*(1.f-f1), wC=(1.f-f0)*f1, wD=f0*f1;
    redAdd2(&g_acc3[(base  )*64+2*lane], wA*xs.x, wA*xs.y);
    redAdd2(&g_acc3[(base+1)*64+2*lane], wB*xs.x, wB*xs.y);
    redAdd2(&g_acc3[(base+5)*64+2*lane], wC*xs.x, wC*xs.y);
    redAdd2(&g_acc3[(base+6)*64+2*lane], wD*xs.x, wD*xs.y);
    if(lane==0) redAddF(&g_deg3[b],1.f);
}

// ---------------- final 2x2 pool ----------------
__global__ void k_fpool(){
    int idx=blockIdx.x*blockDim.x+threadIdx.x;
    if(idx>=S2C*64) return;
    int n=idx>>6, f=idx&63;
    if(g_cnt2[n]<=0.f) return;
    float qx=g_ppos2[2*n], qy=g_ppos2[2*n+1];
    int c0=min(max((int)floorf(qx/14.f),0),1);
    int c1=min(max((int)floorf(qy/14.f),0),1);
    int cl=(n/25)*4+c1*2+c0;
    redMaxU(&g_px3[cl*64+f], encf(g_x3o[idx]));
    if(f==0) redAddF(&g_cnt3[cl],1.f);
}

// ---------------- head: FC(256->128) + elu + FC(128->10) + log_softmax ----------------
__global__ void k_head(const float* __restrict__ fw1, const float* __restrict__ fb1,
                       const float* __restrict__ fw2, const float* __restrict__ fb2,
                       float* __restrict__ out){
    __shared__ float in[256];
    __shared__ float h[128];
    __shared__ float lg[10];
    __shared__ float lse;
    int b=blockIdx.x, t=threadIdx.x;
    for(int i=t;i<256;i+=128){
        int q=i>>6, f=i&63;
        int cl=b*4+q;
        in[i]=(g_cnt3[cl]>0.f)? decf(g_px3[cl*64+f]) : 0.f;
    }
    __syncthreads();
    float s=fb1[t];
    for(int i=0;i<256;i++) s+=in[i]*fw1[t*256+i];
    h[t]=eluf(s);
    __syncthreads();
    if(t<10){
        float l=fb2[t];
        for(int i=0;i<128;i++) l+=h[i]*fw2[t*128+i];
        lg[t]=l;
    }
    __syncthreads();
    if(t==0){
        float m=lg[0];
        for(int i=1;i<10;i++) m=fmaxf(m,lg[i]);
        float ss=0.f;
        for(int i=0;i<10;i++) ss+=expf(lg[i]-m);
        lse=m+logf(ss);
    }
    __syncthreads();
    if(t<10) out[b*10+t]=lg[t]-lse;
}

// ---------------- launch ----------------
extern "C" void kernel_launch(void* const* d_in, const int* in_sizes, int n_in,
                              void* d_out, int out_size){
    const float* x   =(const float*)d_in[0];
    const float* pos =(const float*)d_in[1];
    const int*   src =(const int*)  d_in[2];
    const int*   dst =(const int*)  d_in[3];
    const float* W1  =(const float*)d_in[4];
    const float* r1  =(const float*)d_in[5];
    const float* b1  =(const float*)d_in[6];
    const float* W2  =(const float*)d_in[7];
    const float* r2  =(const float*)d_in[8];
    const float* b2  =(const float*)d_in[9];
    const float* W3  =(const float*)d_in[10];
    const float* r3  =(const float*)d_in[11];
    const float* b3  =(const float*)d_in[12];
    const float* fw1 =(const float*)d_in[13];
    const float* fb1 =(const float*)d_in[14];
    const float* fw2 =(const float*)d_in[15];
    const float* fb2 =(const float*)d_in[16];
    float* out=(float*)d_out;

    float *pA2,*pX2,*pD2,*pX2o,*pA3,*pX3,*pD3,*pX3o;
    cudaGetSymbolAddress((void**)&pA2,  g_acc2);
    cudaGetSymbolAddress((void**)&pX2,  g_x2);
    cudaGetSymbolAddress((void**)&pD2,  g_deg2);
    cudaGetSymbolAddress((void**)&pX2o, g_x2o);
    cudaGetSymbolAddress((void**)&pA3,  g_acc3);
    cudaGetSymbolAddress((void**)&pX3,  g_x3);
    cudaGetSymbolAddress((void**)&pD3,  g_deg3);
    cudaGetSymbolAddress((void**)&pX3o, g_x3o);

    k_reset<<<2048,256>>>();
    k_amax0<<<EE/256,256>>>(pos,src,dst);
    k_scatter1<<<EE/256,256>>>(x,pos,src,dst);
    k_conv1<<<(NN*32)/256,256>>>(x,W1,r1,b1);
    k_pool1<<<(NN*32)/256,256>>>(pos);
    k_fin1<<<(S1C*32)/256,256>>>();
    k_clear1<<<EE/256,256>>>(src,dst);
    k_dedup1<<<EE/256,256>>>(src,dst);
    k_scatter2<<<EE/16,256>>>(src,dst);
    k_conv<800,32><<<S1C/64,256>>>(pA2,pX2,pD2,W2,r2,b2,pX2o);
    k_pool2<<<(S1C*64)/256,256>>>();
    k_fin2<<<(S2C*64)/256,256>>>();
    k_clear2<<<EE/256,256>>>(src,dst);
    k_dedup2<<<EE/256,256>>>(src,dst);
    k_scatter3<<<EE/8,256>>>(src,dst);
    k_conv<1600,64><<<S2C/64,256>>>(pA3,pX3,pD3,W3,r3,b3,pX3o);
    k_fpool<<<(S2C*64)/256,256>>>();
    k_head<<<BB,128>>>(fw1,fb1,fw2,fb2,out);
}

// round 3
// speedup vs baseline: 1.7305x; 1.5413x over previous
#include <cuda_runtime.h>

#define NN   76800
#define EE   1425408
#define BB   1024
#define EPG  1392
#define S1C  36864
#define S2C  25600

// ---------------- device scratch ----------------
__device__ float g_acc1[25*NN];
__device__ float g_deg1[NN];
__device__ float g_x1[NN*32];
__device__ unsigned char g_cl1[NN];       // local cluster id 0..35
__device__ float g_x2[S1C*32];
__device__ float g_cnt1[S1C];
__device__ float g_ppos1[S1C*2];
__device__ unsigned g_el1[EE];
__device__ int   g_ecnt1[BB];
__device__ float g_deg2[S1C];
__device__ float g_acc2[25*S1C*32];
__device__ float g_x2o[S1C*64];
__device__ unsigned char g_cl2[S1C];      // local cluster id 0..24
__device__ float g_x3[S2C*64];
__device__ float g_cnt2[S2C];
__device__ float g_ppos2[S2C*2];
__device__ unsigned g_el2[EE];
__device__ int   g_ecnt2[BB];
__device__ float g_deg3[S2C];
__device__ float g_acc3[25*S2C*64];
__device__ float g_x3o[S2C*64];
__device__ unsigned g_amax[4];

// ---------------- helpers ----------------
__device__ __forceinline__ unsigned encf(float f){
    unsigned u=__float_as_uint(f);
    return (u&0x80000000u)? ~u : (u|0x80000000u);
}
__device__ __forceinline__ float decf(unsigned u){
    return (u&0x80000000u)? __uint_as_float(u&0x7FFFFFFFu) : __uint_as_float(~u);
}
__device__ __forceinline__ float eluf(float x){ return x>0.f ? x : expm1f(x); }

__device__ __forceinline__ void redAddF(float* p, float v){
    asm volatile("red.global.add.f32 [%0], %1;" :: "l"(p), "f"(v) : "memory");
}
__device__ __forceinline__ void red4(float* p, float a, float b, float c, float d){
    asm volatile("red.global.add.v4.f32 [%0], {%1,%2,%3,%4};"
                 :: "l"(p), "f"(a), "f"(b), "f"(c), "f"(d) : "memory");
}
__device__ __forceinline__ void redMaxU(unsigned* p, unsigned v){
    asm volatile("red.global.max.u32 [%0], %1;" :: "l"(p), "r"(v) : "memory");
}

// packed f32x2 ops
typedef unsigned long long ull;
__device__ __forceinline__ ull pk2(float x, float y){
    ull r; asm("mov.b64 %0, {%1, %2};" : "=l"(r) : "f"(x), "f"(y)); return r;
}
__device__ __forceinline__ void upk2(float& x, float& y, ull v){
    asm("mov.b64 {%0, %1}, %2;" : "=f"(x), "=f"(y) : "l"(v));
}
__device__ __forceinline__ void fma2(ull& d, ull a, ull b){
    asm("fma.rn.f32x2 %0, %1, %2, %3;" : "=l"(d) : "l"(a), "l"(b), "l"(d));
}
__device__ __forceinline__ void mul2(ull& d, ull a, ull b){
    asm("mul.rn.f32x2 %0, %1, %2;" : "=l"(d) : "l"(a), "l"(b));
}

// ---------------- reset (acc arrays + deg1 + amax only) ----------------
__global__ void k_reset(){
    size_t i=(size_t)blockIdx.x*blockDim.x+threadIdx.x;
    size_t st=(size_t)gridDim.x*blockDim.x;
    float4 z=make_float4(0.f,0.f,0.f,0.f);
#define ZZ(ptr,n4) for(size_t j=i;j<(size_t)(n4);j+=st) ((float4*)(ptr))[j]=z;
    ZZ(g_acc1,  480000)
    ZZ(g_deg1,  19200)
    ZZ(g_acc2,  7372800)
    ZZ(g_acc3,  10240000)
#undef ZZ
    if(i==0){ g_amax[0]=0u; g_amax[1]=0u; g_amax[2]=0u; g_amax[3]=0u; }
}

// ---------------- stage-1 amax (per graph) ----------------
__global__ void k_amax0g(const float* __restrict__ pos, const int* __restrict__ src,
                         const int* __restrict__ dst){
    int g=blockIdx.x, t=threadIdx.x;
    __shared__ unsigned wm[8];
    unsigned cand=0u;
    for(int i=t;i<EPG;i+=256){
        int e=g*EPG+i;
        int s=src[e], d=dst[e];
        float c0=fabsf(pos[2*s]-pos[2*d]);
        float c1=fabsf(pos[2*s+1]-pos[2*d+1]);
        cand=max(cand,__float_as_uint(fmaxf(c0,c1)));
    }
    unsigned m=__reduce_max_sync(0xffffffffu,cand);
    if((t&31)==0) wm[t>>5]=m;
    __syncthreads();
    if(t==0){
        unsigned mm=0;
        #pragma unroll
        for(int i=0;i<8;i++) mm=max(mm,wm[i]);
        redMaxU(&g_amax[0],mm);
    }
}

// ---------------- stage-1 scatter (Fin=1) ----------------
__global__ void k_scatter1(const float* __restrict__ x, const float* __restrict__ pos,
                           const int* __restrict__ src, const int* __restrict__ dst){
    int e=blockIdx.x*blockDim.x+threadIdx.x;
    if(e>=EE) return;
    int s=src[e], d=dst[e];
    float amax=fmaxf(__uint_as_float(g_amax[0]),1e-12f);
    float inv=0.5f/amax;
    float p0=(pos[2*s]-pos[2*d])*inv+0.5f;
    float p1=(pos[2*s+1]-pos[2*d+1])*inv+0.5f;
    float v0=fminf(fmaxf(p0,0.f),1.f)*4.f;
    float v1=fminf(fmaxf(p1,0.f),1.f)*4.f;
    float b0=fminf(floorf(v0),3.f), b1=fminf(floorf(v1),3.f);
    int i0=(int)b0, i1=(int)b1;
    float f0=v0-b0, f1=v1-b1;
    float xs=x[s];
    int k0=i0+5*i1;
    float* base=&g_acc1[d*25+k0];
    redAddF(base,   (1.f-f0)*(1.f-f1)*xs);
    redAddF(base+1, f0*(1.f-f1)*xs);
    redAddF(base+5, (1.f-f0)*f1*xs);
    redAddF(base+6, f0*f1*xs);
    redAddF(&g_deg1[d],1.f);
}

// ---------------- conv1 (Fin=1 -> 32), warp per node, W1 in smem ----------------
__global__ __launch_bounds__(256) void k_conv1(const float* __restrict__ x,
        const float* __restrict__ W1, const float* __restrict__ r1,
        const float* __restrict__ b1){
    __shared__ float W1s[800];
    __shared__ float r1s[32], b1s[32];
    int t=threadIdx.x;
    for(int i=t;i<800;i+=256) W1s[i]=W1[i];
    if(t<32){ r1s[t]=r1[t]; b1s[t]=b1[t]; }
    __syncthreads();
    int n=blockIdx.x*8+(t>>5);
    int o=t&31;
    const float* ar=&g_acc1[n*25];
    float s=0.f;
#pragma unroll
    for(int k=0;k<25;k++) s+=ar[k]*W1s[k*32+o];
    s=s/fmaxf(g_deg1[n],1.f)+x[n]*r1s[o]+b1s[o];
    g_x1[n*32+o]=eluf(s);
}

// ---------------- pool1 + fin1 fused (per graph) ----------------
__global__ void k_pool1g(const float* __restrict__ pos){
    int g=blockIdx.x, t=threadIdx.x;
    __shared__ unsigned px[36*32];
    __shared__ float cnt[36], psx[36], psy[36];
    __shared__ unsigned char cl[75];
    for(int i=t;i<36*32;i+=256) px[i]=encf(-1e30f);
    if(t<36){ cnt[t]=0.f; psx[t]=0.f; psy[t]=0.f; }
    __syncthreads();
    if(t<75){
        float qx=pos[(g*75+t)*2], qy=pos[(g*75+t)*2+1];
        int c0=min(max((int)floorf(qx/5.f),0),5);
        int c1=min(max((int)floorf(qy/5.f),0),5);
        int c=c1*6+c0;
        cl[t]=(unsigned char)c;
        g_cl1[g*75+t]=(unsigned char)c;
        atomicAdd(&cnt[c],1.f);
        atomicAdd(&psx[c],qx);
        atomicAdd(&psy[c],qy);
    }
    __syncthreads();
    for(int i=t;i<75*32;i+=256){
        int n=i>>5, f=i&31;
        atomicMax(&px[cl[n]*32+f], encf(g_x1[(g*75+n)*32+f]));
    }
    __syncthreads();
    for(int i=t;i<36*32;i+=256){
        int s=i>>5, f=i&31;
        float c=cnt[s];
        g_x2[(g*36+s)*32+f]=(c>0.f)? decf(px[i]) : 0.f;
        if(f==0){
            g_cnt1[g*36+s]=c;
            float ic=1.f/fmaxf(c,1.f);
            g_ppos1[(g*36+s)*2]=psx[s]*ic;
            g_ppos1[(g*36+s)*2+1]=psy[s]*ic;
        }
    }
}

// ---------------- dedup1 (per graph, smem bitmask) -> compact list ----------------
__global__ void k_dedup1g(const int* __restrict__ src, const int* __restrict__ dst){
    int g=blockIdx.x, t=threadIdx.x;
    __shared__ unsigned bm[41];
    __shared__ float deg[36], ppx[36], ppy[36];
    __shared__ unsigned char cl[75];
    __shared__ int cnt;
    __shared__ unsigned cmax;
    if(t<41) bm[t]=0u;
    if(t<36){ deg[t]=0.f; ppx[t]=g_ppos1[(g*36+t)*2]; ppy[t]=g_ppos1[(g*36+t)*2+1]; }
    if(t<75) cl[t]=g_cl1[g*75+t];
    if(t==0){ cnt=0; cmax=0u; }
    __syncthreads();
    for(int i=t;i<EPG;i+=256){
        int e=g*EPG+i;
        int a=cl[src[e]-g*75], b=cl[dst[e]-g*75];
        if(a!=b){
            int key=a*36+b;
            unsigned bit=1u<<(key&31);
            if(!(atomicOr(&bm[key>>5],bit)&bit)){
                int idx=atomicAdd(&cnt,1);
                g_el1[g*EPG+idx]=(unsigned)a|((unsigned)b<<8);
                atomicAdd(&deg[b],1.f);
                float c0=fabsf(ppx[a]-ppx[b]), c1=fabsf(ppy[a]-ppy[b]);
                atomicMax(&cmax,__float_as_uint(fmaxf(c0,c1)));
            }
        }
    }
    __syncthreads();
    if(t<36) g_deg2[g*36+t]=deg[t];
    if(t==0){ g_ecnt1[g]=cnt; redMaxU(&g_amax[1],cmax); }
}

// ---------------- stage-2 scatter: 8 lanes/edge, red.v4 ----------------
__global__ void k_scatter2(){
    int t=blockIdx.x*blockDim.x+threadIdx.x;
    int e=t>>3, lane=t&7;
    int g=e/EPG, i=e-g*EPG;
    if(i>=g_ecnt1[g]) return;
    unsigned r=g_el1[e];
    int a=r&255, b=(r>>8)&255;
    int ga=g*36+a, gb=g*36+b;
    float amax=fmaxf(__uint_as_float(g_amax[1]),1e-12f);
    float inv=0.5f/amax;
    float p0=(g_ppos1[ga*2]-g_ppos1[gb*2])*inv+0.5f;
    float p1=(g_ppos1[ga*2+1]-g_ppos1[gb*2+1])*inv+0.5f;
    float v0=fminf(fmaxf(p0,0.f),1.f)*4.f;
    float v1=fminf(fmaxf(p1,0.f),1.f)*4.f;
    float b0=fminf(floorf(v0),3.f), b1f=fminf(floorf(v1),3.f);
    int i0=(int)b0, i1=(int)b1f;
    float f0=v0-b0, f1=v1-b1f;
    float wA=(1.f-f0)*(1.f-f1), wB=f0*(1.f-f1), wC=(1.f-f0)*f1, wD=f0*f1;
    float4 xs=*(const float4*)&g_x2[ga*32+lane*4];
    float* base=&g_acc2[((size_t)gb*25+(i0+5*i1))*32+lane*4];
    red4(base,       wA*xs.x, wA*xs.y, wA*xs.z, wA*xs.w);
    red4(base+32,    wB*xs.x, wB*xs.y, wB*xs.z, wB*xs.w);
    red4(base+5*32,  wC*xs.x, wC*xs.y, wC*xs.z, wC*xs.w);
    red4(base+6*32,  wD*xs.x, wD*xs.y, wD*xs.z, wD*xs.w);
}

// ---------------- tiled SGEMM conv with packed f32x2 FMA ----------------
// out = elu((A@W)/deg + X@R + b). 64x64 tile, BK=16, 256 thr, 4x4 per thread.
template<int KK,int FIN>
__global__ __launch_bounds__(256) void k_conv(
    const float* __restrict__ A, const float* __restrict__ Xin,
    const float* __restrict__ deg,
    const float* __restrict__ W, const float* __restrict__ R,
    const float* __restrict__ Bv, float* __restrict__ Out)
{
    __shared__ float As[16][68];   // 68 keeps rows 16B-aligned (68*4=272)
    __shared__ float Ws[16][64];
    int t=threadIdx.x;
    int n0=blockIdx.x*64;
    int tx=t&15, ty=t>>4;
    int lr=t>>2, lc=(t&3)*4;
    ull c2[4][2];
#pragma unroll
    for(int i=0;i<4;i++){ c2[i][0]=0ULL; c2[i][1]=0ULL; }

    for(int phase=0;phase<2;phase++){
        const float* Ap = phase? Xin : A;
        const float* Wp = phase? R   : W;
        int kk  = phase? FIN : KK;
        int ldA = phase? FIN : KK;
        if(phase==1){
#pragma unroll
            for(int i=0;i<4;i++){
                float invd=1.f/fmaxf(deg[n0+ty*4+i],1.f);
                ull iv=pk2(invd,invd);
                mul2(c2[i][0],c2[i][0],iv);
                mul2(c2[i][1],c2[i][1],iv);
            }
        }
        for(int j0=0;j0<kk;j0+=16){
            __syncthreads();
            float4 av=*(const float4*)(Ap+(size_t)(n0+lr)*ldA+j0+lc);
            As[lc+0][lr]=av.x; As[lc+1][lr]=av.y; As[lc+2][lr]=av.z; As[lc+3][lr]=av.w;
            *(float4*)&Ws[ty][tx*4]=*(const float4*)(Wp+(size_t)(j0+ty)*64+tx*4);
            __syncthreads();
#pragma unroll
            for(int k=0;k<16;k++){
                float4 a=*(const float4*)&As[k][ty*4];
                ulonglong2 w=*(const ulonglong2*)&Ws[k][tx*4];
                ull ap;
                ap=pk2(a.x,a.x); fma2(c2[0][0],ap,w.x); fma2(c2[0][1],ap,w.y);
                ap=pk2(a.y,a.y); fma2(c2[1][0],ap,w.x); fma2(c2[1][1],ap,w.y);
                ap=pk2(a.z,a.z); fma2(c2[2][0],ap,w.x); fma2(c2[2][1],ap,w.y);
                ap=pk2(a.w,a.w); fma2(c2[3][0],ap,w.x); fma2(c2[3][1],ap,w.y);
            }
        }
    }
    float4 bv=*(const float4*)&Bv[tx*4];
#pragma unroll
    for(int i=0;i<4;i++){
        int n=n0+ty*4+i;
        float x0,x1,x2v,x3v;
        upk2(x0,x1,c2[i][0]);
        upk2(x2v,x3v,c2[i][1]);
        float4 o;
        o.x=eluf(x0+bv.x); o.y=eluf(x1+bv.y);
        o.z=eluf(x2v+bv.z); o.w=eluf(x3v+bv.w);
        *(float4*)&Out[(size_t)n*64+tx*4]=o;
    }
}

// ---------------- pool2 + fin2 fused (per graph) ----------------
__global__ void k_pool2g(){
    int g=blockIdx.x, t=threadIdx.x;
    __shared__ unsigned px[25*64];
    __shared__ float cnt[25], psx[25], psy[25];
    __shared__ unsigned char cl[36], vld[36];
    for(int i=t;i<25*64;i+=256) px[i]=encf(-1e30f);
    if(t<25){ cnt[t]=0.f; psx[t]=0.f; psy[t]=0.f; }
    __syncthreads();
    if(t<36){
        float qx=g_ppos1[(g*36+t)*2], qy=g_ppos1[(g*36+t)*2+1];
        int c0=min(max((int)floorf(qx/7.f),0),4);
        int c1=min(max((int)floorf(qy/7.f),0),4);
        int c=c1*5+c0;
        cl[t]=(unsigned char)c;
        g_cl2[g*36+t]=(unsigned char)c;
        unsigned char v=(g_cnt1[g*36+t]>0.f)?1:0;
        vld[t]=v;
        if(v){ atomicAdd(&cnt[c],1.f); atomicAdd(&psx[c],qx); atomicAdd(&psy[c],qy); }
    }
    __syncthreads();
    for(int i=t;i<36*64;i+=256){
        int s=i>>6, f=i&63;
        if(vld[s]) atomicMax(&px[cl[s]*64+f], encf(g_x2o[(g*36+s)*64+f]));
    }
    __syncthreads();
    for(int i=t;i<25*64;i+=256){
        int s=i>>6, f=i&63;
        float c=cnt[s];
        g_x3[(g*25+s)*64+f]=(c>0.f)? decf(px[i]) : 0.f;
        if(f==0){
            g_cnt2[g*25+s]=c;
            float ic=1.f/fmaxf(c,1.f);
            g_ppos2[(g*25+s)*2]=psx[s]*ic;
            g_ppos2[(g*25+s)*2+1]=psy[s]*ic;
        }
    }
}

// ---------------- dedup2 (per graph) ----------------
__global__ void k_dedup2g(){
    int g=blockIdx.x, t=threadIdx.x;
    __shared__ unsigned bm[20];
    __shared__ float deg[25], ppx[25], ppy[25];
    __shared__ unsigned char cl[36];
    __shared__ int cnt;
    __shared__ unsigned cmax;
    if(t<20) bm[t]=0u;
    if(t<25){ deg[t]=0.f; ppx[t]=g_ppos2[(g*25+t)*2]; ppy[t]=g_ppos2[(g*25+t)*2+1]; }
    if(t<36) cl[t]=g_cl2[g*36+t];
    if(t==0){ cnt=0; cmax=0u; }
    __syncthreads();
    int ec=g_ecnt1[g];
    for(int i=t;i<ec;i+=256){
        unsigned r=g_el1[g*EPG+i];
        int a=cl[r&255], b=cl[(r>>8)&255];
        if(a!=b){
            int key=a*25+b;
            unsigned bit=1u<<(key&31);
            if(!(atomicOr(&bm[key>>5],bit)&bit)){
                int idx=atomicAdd(&cnt,1);
                g_el2[g*EPG+idx]=(unsigned)a|((unsigned)b<<8);
                atomicAdd(&deg[b],1.f);
                float c0=fabsf(ppx[a]-ppx[b]), c1=fabsf(ppy[a]-ppy[b]);
                atomicMax(&cmax,__float_as_uint(fmaxf(c0,c1)));
            }
        }
    }
    __syncthreads();
    if(t<25) g_deg3[g*25+t]=deg[t];
    if(t==0){ g_ecnt2[g]=cnt; redMaxU(&g_amax[2],cmax); }
}

// ---------------- stage-3 scatter: 16 lanes/edge, red.v4 ----------------
__global__ void k_scatter3(){
    int t=blockIdx.x*blockDim.x+threadIdx.x;
    int e=t>>4, lane=t&15;
    int g=e/EPG, i=e-g*EPG;
    if(i>=g_ecnt2[g]) return;
    unsigned r=g_el2[e];
    int a=r&255, b=(r>>8)&255;
    int ga=g*25+a, gb=g*25+b;
    float amax=fmaxf(__uint_as_float(g_amax[2]),1e-12f);
    float inv=0.5f/amax;
    float p0=(g_ppos2[ga*2]-g_ppos2[gb*2])*inv+0.5f;
    float p1=(g_ppos2[ga*2+1]-g_ppos2[gb*2+1])*inv+0.5f;
    float v0=fminf(fmaxf(p0,0.f),1.f)*4.f;
    float v1=fminf(fmaxf(p1,0.f),1.f)*4.f;
    float b0=fminf(floorf(v0),3.f), b1f=fminf(floorf(v1),3.f);
    int i0=(int)b0, i1=(int)b1f;
    float f0=v0-b0, f1=v1-b1f;
    float wA=(1.f-f0)*(1.f-f1), wB=f0*(1.f-f1), wC=(1.f-f0)*f1, wD=f0*f1;
    float4 xs=*(const float4*)&g_x3[ga*64+lane*4];
    float* base=&g_acc3[((size_t)gb*25+(i0+5*i1))*64+lane*4];
    red4(base,       wA*xs.x, wA*xs.y, wA*xs.z, wA*xs.w);
    red4(base+64,    wB*xs.x, wB*xs.y, wB*xs.z, wB*xs.w);
    red4(base+5*64,  wC*xs.x, wC*xs.y, wC*xs.z, wC*xs.w);
    red4(base+6*64,  wD*xs.x, wD*xs.y, wD*xs.z, wD*xs.w);
}

// ---------------- fused final pool + FC head (per graph) ----------------
__global__ __launch_bounds__(128) void k_headg(const float* __restrict__ fw1,
        const float* __restrict__ fb1, const float* __restrict__ fw2,
        const float* __restrict__ fb2, float* __restrict__ out){
    __shared__ unsigned enc4[4*64];
    __shared__ unsigned any[4];
    __shared__ float in[256];
    __shared__ float h[128];
    __shared__ float lg[10];
    __shared__ float lse;
    int g=blockIdx.x, t=threadIdx.x;
    for(int i=t;i<256;i+=128) enc4[i]=encf(-1e30f);
    if(t<4) any[t]=0u;
    __syncthreads();
    for(int i=t;i<25*64;i+=128){
        int n=i>>6, f=i&63;
        if(g_cnt2[g*25+n]>0.f){
            float qx=g_ppos2[(g*25+n)*2], qy=g_ppos2[(g*25+n)*2+1];
            int c0=min(max((int)floorf(qx/14.f),0),1);
            int c1=min(max((int)floorf(qy/14.f),0),1);
            int cell=c1*2+c0;
            atomicMax(&enc4[cell*64+f], encf(g_x3o[(g*25+n)*64+f]));
            if(f==0) atomicOr(&any[cell],1u);
        }
    }
    __syncthreads();
    for(int i=t;i<256;i+=128)
        in[i]=any[i>>6]? decf(enc4[i]) : 0.f;
    __syncthreads();
    float s=fb1[t];
    const float4* wr=(const float4*)(fw1+(size_t)t*256);
#pragma unroll 8
    for(int i=0;i<64;i++){
        float4 w=wr[i];
        const float4 v=*(const float4*)&in[i*4];
        s+=w.x*v.x+w.y*v.y+w.z*v.z+w.w*v.w;
    }
    h[t]=eluf(s);
    __syncthreads();
    if(t<10){
        float l=fb2[t];
        for(int i=0;i<128;i++) l+=h[i]*fw2[t*128+i];
        lg[t]=l;
    }
    __syncthreads();
    if(t==0){
        float m=lg[0];
        for(int i=1;i<10;i++) m=fmaxf(m,lg[i]);
        float ss=0.f;
        for(int i=0;i<10;i++) ss+=expf(lg[i]-m);
        lse=m+logf(ss);
    }
    __syncthreads();
    if(t<10) out[g*10+t]=lg[t]-lse;
}

// ---------------- launch ----------------
extern "C" void kernel_launch(void* const* d_in, const int* in_sizes, int n_in,
                              void* d_out, int out_size){
    const float* x   =(const float*)d_in[0];
    const float* pos =(const float*)d_in[1];
    const int*   src =(const int*)  d_in[2];
    const int*   dst =(const int*)  d_in[3];
    const float* W1  =(const float*)d_in[4];
    const float* r1  =(const float*)d_in[5];
    const float* b1  =(const float*)d_in[6];
    const float* W2  =(const float*)d_in[7];
    const float* r2  =(const float*)d_in[8];
    const float* b2  =(const float*)d_in[9];
    const float* W3  =(const float*)d_in[10];
    const float* r3  =(const float*)d_in[11];
    const float* b3  =(const float*)d_in[12];
    const float* fw1 =(const float*)d_in[13];
    const float* fb1 =(const float*)d_in[14];
    const float* fw2 =(const float*)d_in[15];
    const float* fb2 =(const float*)d_in[16];
    float* out=(float*)d_out;

    float *pA2,*pX2,*pD2,*pX2o,*pA3,*pX3,*pD3,*pX3o;
    cudaGetSymbolAddress((void**)&pA2,  g_acc2);
    cudaGetSymbolAddress((void**)&pX2,  g_x2);
    cudaGetSymbolAddress((void**)&pD2,  g_deg2);
    cudaGetSymbolAddress((void**)&pX2o, g_x2o);
    cudaGetSymbolAddress((void**)&pA3,  g_acc3);
    cudaGetSymbolAddress((void**)&pX3,  g_x3);
    cudaGetSymbolAddress((void**)&pD3,  g_deg3);
    cudaGetSymbolAddress((void**)&pX3o, g_x3o);

    k_reset<<<2048,256>>>();
    k_amax0g<<<BB,256>>>(pos,src,dst);
    k_scatter1<<<EE/256,256>>>(x,pos,src,dst);
    k_conv1<<<NN/8,256>>>(x,W1,r1,b1);
    k_pool1g<<<BB,256>>>(pos);
    k_dedup1g<<<BB,256>>>(src,dst);
    k_scatter2<<<(BB*EPG*8)/256,256>>>();
    k_conv<800,32><<<S1C/64,256>>>(pA2,pX2,pD2,W2,r2,b2,pX2o);
    k_pool2g<<<BB,256>>>();
    k_dedup2g<<<BB,256>>>();
    k_scatter3<<<(BB*EPG*16)/256,256>>>();
    k_conv<1600,64><<<S2C/64,256>>>(pA3,pX3,pD3,W3,r3,b3,pX3o);
    k_headg<<<BB,128>>>(fw1,fb1,fw2,fb2,out);
}

// round 4
// speedup vs baseline: 2.3734x; 1.3715x over previous
#include <cuda_runtime.h>

#define NN   76800
#define EE   1425408
#define BB   1024
#define EPG  1392
#define S1C  36864
#define S2C  25600

// ---------------- device scratch ----------------
__device__ float g_x2[S1C*32];
__device__ float g_cnt1[S1C];
__device__ float g_ppos1[S1C*2];
__device__ unsigned char g_cl1[NN];
__device__ unsigned g_el1[EE];
__device__ int   g_ecnt1[BB];
__device__ float g_deg2[S1C];
__device__ float g_acc2[25*S1C*32];
__device__ float g_x2o[S1C*64];
__device__ unsigned char g_cl2[S1C];
__device__ float g_x3[S2C*64];
__device__ float g_cnt2[S2C];
__device__ float g_ppos2[S2C*2];
__device__ unsigned g_el2[EE];
__device__ int   g_ecnt2[BB];
__device__ float g_deg3[S2C];
__device__ float g_acc3[25*S2C*64];
__device__ float g_x3o[S2C*64];
__device__ unsigned g_amax[4];

// ---------------- helpers ----------------
__device__ __forceinline__ unsigned encf(float f){
    unsigned u=__float_as_uint(f);
    return (u&0x80000000u)? ~u : (u|0x80000000u);
}
__device__ __forceinline__ float decf(unsigned u){
    return (u&0x80000000u)? __uint_as_float(u&0x7FFFFFFFu) : __uint_as_float(~u);
}
__device__ __forceinline__ float eluf(float x){ return x>0.f ? x : expm1f(x); }

__device__ __forceinline__ void red4(float* p, float a, float b, float c, float d){
    asm volatile("red.global.add.v4.f32 [%0], {%1,%2,%3,%4};"
                 :: "l"(p), "f"(a), "f"(b), "f"(c), "f"(d) : "memory");
}
__device__ __forceinline__ void redMaxU(unsigned* p, unsigned v){
    asm volatile("red.global.max.u32 [%0], %1;" :: "l"(p), "r"(v) : "memory");
}
__device__ __forceinline__ unsigned tf32c(float f){
    unsigned r; asm("cvt.rna.tf32.f32 %0, %1;" : "=r"(r) : "f"(f)); return r;
}
__device__ __forceinline__ void mma_tf32(float* d, unsigned a0,unsigned a1,unsigned a2,unsigned a3,
                                         unsigned b0, unsigned b1){
    asm("mma.sync.aligned.m16n8k8.row.col.f32.tf32.tf32.f32 "
        "{%0,%1,%2,%3}, {%4,%5,%6,%7}, {%8,%9}, {%0,%1,%2,%3};"
        : "+f"(d[0]),"+f"(d[1]),"+f"(d[2]),"+f"(d[3])
        : "r"(a0),"r"(a1),"r"(a2),"r"(a3),"r"(b0),"r"(b1));
}

// ---------------- reset (acc2/acc3 + amax only) ----------------
__global__ void k_reset(){
    size_t i=(size_t)blockIdx.x*blockDim.x+threadIdx.x;
    size_t st=(size_t)gridDim.x*blockDim.x;
    float4 z=make_float4(0.f,0.f,0.f,0.f);
    for(size_t j=i;j<7372800u;j+=st) ((float4*)g_acc2)[j]=z;
    for(size_t j=i;j<10240000u;j+=st) ((float4*)g_acc3)[j]=z;
    if(i==0){ g_amax[0]=0u; g_amax[1]=0u; g_amax[2]=0u; g_amax[3]=0u; }
}

// ---------------- stage-1 global amax ----------------
__global__ void k_amax0g(const float* __restrict__ pos, const int* __restrict__ src,
                         const int* __restrict__ dst){
    int g=blockIdx.x, t=threadIdx.x;
    __shared__ unsigned wm[8];
    unsigned cand=0u;
    for(int i=t;i<EPG;i+=256){
        int e=g*EPG+i;
        int s=src[e], d=dst[e];
        float c0=fabsf(pos[2*s]-pos[2*d]);
        float c1=fabsf(pos[2*s+1]-pos[2*d+1]);
        cand=max(cand,__float_as_uint(fmaxf(c0,c1)));
    }
    unsigned m=__reduce_max_sync(0xffffffffu,cand);
    if((t&31)==0) wm[t>>5]=m;
    __syncthreads();
    if(t==0){
        unsigned mm=0;
        #pragma unroll
        for(int i=0;i<8;i++) mm=max(mm,wm[i]);
        redMaxU(&g_amax[0],mm);
    }
}

// ---------------- fused stage 1: scatter + conv1 + pool1 (one block per graph) ----------------
__global__ __launch_bounds__(256) void k_stage1(const float* __restrict__ x,
        const float* __restrict__ pos, const int* __restrict__ src,
        const int* __restrict__ dst, const float* __restrict__ W1,
        const float* __restrict__ r1, const float* __restrict__ b1){
    int g=blockIdx.x, t=threadIdx.x;
    __shared__ float acc[75*25];
    __shared__ float deg[75];
    __shared__ float posx[75], posy[75], xin[75];
    __shared__ float W1s[800], r1s[32], b1s[32];
    __shared__ float x1s[75*32];
    __shared__ unsigned px[36*32];
    __shared__ float cnt[36], psx[36], psy[36];
    __shared__ unsigned char cl[75];

    for(int i=t;i<1875;i+=256) acc[i]=0.f;
    for(int i=t;i<800;i+=256) W1s[i]=W1[i];
    if(t<75){
        deg[t]=0.f;
        float2 p=*(const float2*)&pos[(g*75+t)*2];
        posx[t]=p.x; posy[t]=p.y;
        xin[t]=x[g*75+t];
    }
    if(t>=96 && t<128){ r1s[t-96]=r1[t-96]; b1s[t-96]=b1[t-96]; }
    if(t>=128 && t<164){ int c=t-128; cnt[c]=0.f; psx[c]=0.f; psy[c]=0.f; }
    for(int i=t;i<1152;i+=256) px[i]=encf(-1e30f);
    __syncthreads();
    if(t<75){
        int c0=min(max((int)floorf(posx[t]/5.f),0),5);
        int c1=min(max((int)floorf(posy[t]/5.f),0),5);
        int c=c1*6+c0;
        cl[t]=(unsigned char)c;
        atomicAdd(&cnt[c],1.f);
        atomicAdd(&psx[c],posx[t]);
        atomicAdd(&psy[c],posy[t]);
    }
    float amax=fmaxf(__uint_as_float(g_amax[0]),1e-12f);
    float inv=0.5f/amax;
    for(int i=t;i<EPG;i+=256){
        int e=g*EPG+i;
        int s=src[e]-g*75, d=dst[e]-g*75;
        float p0=(posx[s]-posx[d])*inv+0.5f;
        float p1=(posy[s]-posy[d])*inv+0.5f;
        float v0=fminf(fmaxf(p0,0.f),1.f)*4.f;
        float v1=fminf(fmaxf(p1,0.f),1.f)*4.f;
        float b0=fminf(floorf(v0),3.f), b1f=fminf(floorf(v1),3.f);
        int i0=(int)b0, i1=(int)b1f;
        float f0=v0-b0, f1=v1-b1f;
        float xs=xin[s];
        float* base=&acc[d*25+i0+5*i1];
        atomicAdd(base,   (1.f-f0)*(1.f-f1)*xs);
        atomicAdd(base+1, f0*(1.f-f1)*xs);
        atomicAdd(base+5, (1.f-f0)*f1*xs);
        atomicAdd(base+6, f0*f1*xs);
        atomicAdd(&deg[d],1.f);
    }
    __syncthreads();
    for(int i=t;i<2400;i+=256){
        int n=i>>5, o=i&31;
        const float* ar=&acc[n*25];
        float s=0.f;
#pragma unroll
        for(int k=0;k<25;k++) s+=ar[k]*W1s[k*32+o];
        s=s/fmaxf(deg[n],1.f)+xin[n]*r1s[o]+b1s[o];
        x1s[i]=eluf(s);
    }
    __syncthreads();
    for(int i=t;i<2400;i+=256){
        int n=i>>5, f=i&31;
        atomicMax(&px[cl[n]*32+f], encf(x1s[i]));
    }
    __syncthreads();
    for(int i=t;i<1152;i+=256){
        int s=i>>5, f=i&31;
        float c=cnt[s];
        g_x2[(g*36+s)*32+f]=(c>0.f)? decf(px[i]) : 0.f;
        if(f==0){
            g_cnt1[g*36+s]=c;
            float ic=1.f/fmaxf(c,1.f);
            g_ppos1[(g*36+s)*2]=psx[s]*ic;
            g_ppos1[(g*36+s)*2+1]=psy[s]*ic;
        }
    }
    if(t<75) g_cl1[g*75+t]=cl[t];
}

// ---------------- dedup1 (per graph, smem bitmask) -> compact list ----------------
__global__ void k_dedup1g(const int* __restrict__ src, const int* __restrict__ dst){
    int g=blockIdx.x, t=threadIdx.x;
    __shared__ unsigned bm[41];
    __shared__ float deg[36], ppx[36], ppy[36];
    __shared__ unsigned char cl[75];
    __shared__ int cnt;
    __shared__ unsigned cmax;
    if(t<41) bm[t]=0u;
    if(t<36){ deg[t]=0.f; ppx[t]=g_ppos1[(g*36+t)*2]; ppy[t]=g_ppos1[(g*36+t)*2+1]; }
    if(t<75) cl[t]=g_cl1[g*75+t];
    if(t==0){ cnt=0; cmax=0u; }
    __syncthreads();
    for(int i=t;i<EPG;i+=256){
        int e=g*EPG+i;
        int a=cl[src[e]-g*75], b=cl[dst[e]-g*75];
        if(a!=b){
            int key=a*36+b;
            unsigned bit=1u<<(key&31);
            if(!(atomicOr(&bm[key>>5],bit)&bit)){
                int idx=atomicAdd(&cnt,1);
                g_el1[g*EPG+idx]=(unsigned)a|((unsigned)b<<8);
                atomicAdd(&deg[b],1.f);
                float c0=fabsf(ppx[a]-ppx[b]), c1=fabsf(ppy[a]-ppy[b]);
                atomicMax(&cmax,__float_as_uint(fmaxf(c0,c1)));
            }
        }
    }
    __syncthreads();
    if(t<36) g_deg2[g*36+t]=deg[t];
    if(t==0){ g_ecnt1[g]=cnt; redMaxU(&g_amax[1],cmax); }
}

// ---------------- stage-2 scatter: 8 lanes/edge, red.v4 ----------------
__global__ void k_scatter2(){
    int t=blockIdx.x*blockDim.x+threadIdx.x;
    int e=t>>3, lane=t&7;
    int g=e/EPG, i=e-g*EPG;
    if(i>=g_ecnt1[g]) return;
    unsigned r=g_el1[e];
    int a=r&255, b=(r>>8)&255;
    int ga=g*36+a, gb=g*36+b;
    float amax=fmaxf(__uint_as_float(g_amax[1]),1e-12f);
    float inv=0.5f/amax;
    float p0=(g_ppos1[ga*2]-g_ppos1[gb*2])*inv+0.5f;
    float p1=(g_ppos1[ga*2+1]-g_ppos1[gb*2+1])*inv+0.5f;
    float v0=fminf(fmaxf(p0,0.f),1.f)*4.f;
    float v1=fminf(fmaxf(p1,0.f),1.f)*4.f;
    float b0=fminf(floorf(v0),3.f), b1f=fminf(floorf(v1),3.f);
    int i0=(int)b0, i1=(int)b1f;
    float f0=v0-b0, f1=v1-b1f;
    float wA=(1.f-f0)*(1.f-f1), wB=f0*(1.f-f1), wC=(1.f-f0)*f1, wD=f0*f1;
    float4 xs=*(const float4*)&g_x2[ga*32+lane*4];
    float* base=&g_acc2[((size_t)gb*25+(i0+5*i1))*32+lane*4];
    red4(base,       wA*xs.x, wA*xs.y, wA*xs.z, wA*xs.w);
    red4(base+32,    wB*xs.x, wB*xs.y, wB*xs.z, wB*xs.w);
    red4(base+5*32,  wC*xs.x, wC*xs.y, wC*xs.z, wC*xs.w);
    red4(base+6*32,  wD*xs.x, wD*xs.y, wD*xs.z, wD*xs.w);
}

// ---------------- tf32 tensor-core conv GEMM ----------------
// out = elu((A@W)/deg + X@R + b). Tile M=128, N=64, K-tile=32. 256 thr (8 warps).
// Warp w computes rows [n0+w*16, +16) x all 64 cols via 8 m16n8k8 mmas per k8.
template<int KK,int FIN>
__global__ __launch_bounds__(256) void k_convT(
    const float* __restrict__ A, const float* __restrict__ Xin,
    const float* __restrict__ deg,
    const float* __restrict__ W, const float* __restrict__ R,
    const float* __restrict__ Bv, float* __restrict__ Out)
{
    __shared__ unsigned As[32][136];  // A^T, tf32-converted; bank = 8*tig+gid (conflict-free)
    __shared__ unsigned Ws[32][72];   // W, tf32-converted; bank = 8*tig+gid (conflict-free)
    int t=threadIdx.x, lane=t&31, w=t>>5;
    int gid=lane>>2, tig=lane&3;
    int n0=blockIdx.x*128;
    int r0=n0+w*16+gid;
    float C[8][4];
#pragma unroll
    for(int j=0;j<8;j++){ C[j][0]=0.f; C[j][1]=0.f; C[j][2]=0.f; C[j][3]=0.f; }

    for(int phase=0;phase<2;phase++){
        const float* Ap = phase? Xin : A;
        const float* Wp = phase? R   : W;
        int kk  = phase? FIN : KK;
        int ldA = phase? FIN : KK;
        if(phase==1){
            float i0=1.f/fmaxf(deg[r0],1.f);
            float i1=1.f/fmaxf(deg[r0+8],1.f);
#pragma unroll
            for(int j=0;j<8;j++){ C[j][0]*=i0; C[j][1]*=i0; C[j][2]*=i1; C[j][3]*=i1; }
        }
        for(int k0=0;k0<kk;k0+=32){
            __syncthreads();
            {   // A tile: thread t loads row r=t>>1, 16 cols at cb
                int r=t>>1, cb=(t&1)*16;
                const float* srcp=Ap+(size_t)(n0+r)*ldA+k0+cb;
#pragma unroll
                for(int q=0;q<4;q++){
                    float4 v=*(const float4*)(srcp+4*q);
                    As[cb+4*q+0][r]=tf32c(v.x);
                    As[cb+4*q+1][r]=tf32c(v.y);
                    As[cb+4*q+2][r]=tf32c(v.z);
                    As[cb+4*q+3][r]=tf32c(v.w);
                }
            }
            {   // W tile: thread t loads row kr, 8 cols at cb
                int kr=t>>3, cb=(t&7)*8;
                const float* srcw=Wp+(size_t)(k0+kr)*64+cb;
                float4 v0=*(const float4*)(srcw);
                float4 v1=*(const float4*)(srcw+4);
                Ws[kr][cb+0]=tf32c(v0.x); Ws[kr][cb+1]=tf32c(v0.y);
                Ws[kr][cb+2]=tf32c(v0.z); Ws[kr][cb+3]=tf32c(v0.w);
                Ws[kr][cb+4]=tf32c(v1.x); Ws[kr][cb+5]=tf32c(v1.y);
                Ws[kr][cb+6]=tf32c(v1.z); Ws[kr][cb+7]=tf32c(v1.w);
            }
            __syncthreads();
#pragma unroll
            for(int k8=0;k8<32;k8+=8){
                unsigned a0=As[k8+tig  ][w*16+gid];
                unsigned a1=As[k8+tig  ][w*16+8+gid];
                unsigned a2=As[k8+tig+4][w*16+gid];
                unsigned a3=As[k8+tig+4][w*16+8+gid];
#pragma unroll
                for(int j=0;j<8;j++){
                    unsigned b0=Ws[k8+tig  ][j*8+gid];
                    unsigned b1=Ws[k8+tig+4][j*8+gid];
                    mma_tf32(C[j],a0,a1,a2,a3,b0,b1);
                }
            }
        }
    }
#pragma unroll
    for(int j=0;j<8;j++){
        int c=j*8+2*tig;
        float bv0=Bv[c], bv1=Bv[c+1];
        float2 o;
        o.x=eluf(C[j][0]+bv0); o.y=eluf(C[j][1]+bv1);
        *(float2*)&Out[(size_t)r0*64+c]=o;
        o.x=eluf(C[j][2]+bv0); o.y=eluf(C[j][3]+bv1);
        *(float2*)&Out[(size_t)(r0+8)*64+c]=o;
    }
}

// ---------------- pool2 + fin2 fused (per graph) ----------------
__global__ void k_pool2g(){
    int g=blockIdx.x, t=threadIdx.x;
    __shared__ unsigned px[25*64];
    __shared__ float cnt[25], psx[25], psy[25];
    __shared__ unsigned char cl[36], vld[36];
    for(int i=t;i<25*64;i+=256) px[i]=encf(-1e30f);
    if(t<25){ cnt[t]=0.f; psx[t]=0.f; psy[t]=0.f; }
    __syncthreads();
    if(t<36){
        float qx=g_ppos1[(g*36+t)*2], qy=g_ppos1[(g*36+t)*2+1];
        int c0=min(max((int)floorf(qx/7.f),0),4);
        int c1=min(max((int)floorf(qy/7.f),0),4);
        int c=c1*5+c0;
        cl[t]=(unsigned char)c;
        g_cl2[g*36+t]=(unsigned char)c;
        unsigned char v=(g_cnt1[g*36+t]>0.f)?1:0;
        vld[t]=v;
        if(v){ atomicAdd(&cnt[c],1.f); atomicAdd(&psx[c],qx); atomicAdd(&psy[c],qy); }
    }
    __syncthreads();
    for(int i=t;i<36*64;i+=256){
        int s=i>>6, f=i&63;
        if(vld[s]) atomicMax(&px[cl[s]*64+f], encf(g_x2o[(g*36+s)*64+f]));
    }
    __syncthreads();
    for(int i=t;i<25*64;i+=256){
        int s=i>>6, f=i&63;
        float c=cnt[s];
        g_x3[(g*25+s)*64+f]=(c>0.f)? decf(px[i]) : 0.f;
        if(f==0){
            g_cnt2[g*25+s]=c;
            float ic=1.f/fmaxf(c,1.f);
            g_ppos2[(g*25+s)*2]=psx[s]*ic;
            g_ppos2[(g*25+s)*2+1]=psy[s]*ic;
        }
    }
}

// ---------------- dedup2 (per graph) ----------------
__global__ void k_dedup2g(){
    int g=blockIdx.x, t=threadIdx.x;
    __shared__ unsigned bm[20];
    __shared__ float deg[25], ppx[25], ppy[25];
    __shared__ unsigned char cl[36];
    __shared__ int cnt;
    __shared__ unsigned cmax;
    if(t<20) bm[t]=0u;
    if(t<25){ deg[t]=0.f; ppx[t]=g_ppos2[(g*25+t)*2]; ppy[t]=g_ppos2[(g*25+t)*2+1]; }
    if(t<36) cl[t]=g_cl2[g*36+t];
    if(t==0){ cnt=0; cmax=0u; }
    __syncthreads();
    int ec=g_ecnt1[g];
    for(int i=t;i<ec;i+=256){
        unsigned r=g_el1[g*EPG+i];
        int a=cl[r&255], b=cl[(r>>8)&255];
        if(a!=b){
            int key=a*25+b;
            unsigned bit=1u<<(key&31);
            if(!(atomicOr(&bm[key>>5],bit)&bit)){
                int idx=atomicAdd(&cnt,1);
                g_el2[g*EPG+idx]=(unsigned)a|((unsigned)b<<8);
                atomicAdd(&deg[b],1.f);
                float c0=fabsf(ppx[a]-ppx[b]), c1=fabsf(ppy[a]-ppy[b]);
                atomicMax(&cmax,__float_as_uint(fmaxf(c0,c1)));
            }
        }
    }
    __syncthreads();
    if(t<25) g_deg3[g*25+t]=deg[t];
    if(t==0){ g_ecnt2[g]=cnt; redMaxU(&g_amax[2],cmax); }
}

// ---------------- stage-3 scatter: 16 lanes/edge, red.v4 ----------------
__global__ void k_scatter3(){
    int t=blockIdx.x*blockDim.x+threadIdx.x;
    int e=t>>4, lane=t&15;
    int g=e/EPG, i=e-g*EPG;
    if(i>=g_ecnt2[g]) return;
    unsigned r=g_el2[e];
    int a=r&255, b=(r>>8)&255;
    int ga=g*25+a, gb=g*25+b;
    float amax=fmaxf(__uint_as_float(g_amax[2]),1e-12f);
    float inv=0.5f/amax;
    float p0=(g_ppos2[ga*2]-g_ppos2[gb*2])*inv+0.5f;
    float p1=(g_ppos2[ga*2+1]-g_ppos2[gb*2+1])*inv+0.5f;
    float v0=fminf(fmaxf(p0,0.f),1.f)*4.f;
    float v1=fminf(fmaxf(p1,0.f),1.f)*4.f;
    float b0=fminf(floorf(v0),3.f), b1f=fminf(floorf(v1),3.f);
    int i0=(int)b0, i1=(int)b1f;
    float f0=v0-b0, f1=v1-b1f;
    float wA=(1.f-f0)*(1.f-f1), wB=f0*(1.f-f1), wC=(1.f-f0)*f1, wD=f0*f1;
    float4 xs=*(const float4*)&g_x3[ga*64+lane*4];
    float* base=&g_acc3[((size_t)gb*25+(i0+5*i1))*64+lane*4];
    red4(base,       wA*xs.x, wA*xs.y, wA*xs.z, wA*xs.w);
    red4(base+64,    wB*xs.x, wB*xs.y, wB*xs.z, wB*xs.w);
    red4(base+5*64,  wC*xs.x, wC*xs.y, wC*xs.z, wC*xs.w);
    red4(base+6*64,  wD*xs.x, wD*xs.y, wD*xs.z, wD*xs.w);
}

// ---------------- fused final pool + FC head (per graph) ----------------
__global__ __launch_bounds__(128) void k_headg(const float* __restrict__ fw1,
        const float* __restrict__ fb1, const float* __restrict__ fw2,
        const float* __restrict__ fb2, float* __restrict__ out){
    __shared__ unsigned enc4[4*64];
    __shared__ unsigned any[4];
    __shared__ float in[256];
    __shared__ float h[128];
    __shared__ float lg[10];
    __shared__ float lse;
    int g=blockIdx.x, t=threadIdx.x;
    for(int i=t;i<256;i+=128) enc4[i]=encf(-1e30f);
    if(t<4) any[t]=0u;
    __syncthreads();
    for(int i=t;i<25*64;i+=128){
        int n=i>>6, f=i&63;
        if(g_cnt2[g*25+n]>0.f){
            float qx=g_ppos2[(g*25+n)*2], qy=g_ppos2[(g*25+n)*2+1];
            int c0=min(max((int)floorf(qx/14.f),0),1);
            int c1=min(max((int)floorf(qy/14.f),0),1);
            int cell=c1*2+c0;
            atomicMax(&enc4[cell*64+f], encf(g_x3o[(g*25+n)*64+f]));
            if(f==0) atomicOr(&any[cell],1u);
        }
    }
    __syncthreads();
    for(int i=t;i<256;i+=128)
        in[i]=any[i>>6]? decf(enc4[i]) : 0.f;
    __syncthreads();
    float s=fb1[t];
    const float4* wr=(const float4*)(fw1+(size_t)t*256);
#pragma unroll 8
    for(int i=0;i<64;i++){
        float4 w=wr[i];
        const float4 v=*(const float4*)&in[i*4];
        s+=w.x*v.x+w.y*v.y+w.z*v.z+w.w*v.w;
    }
    h[t]=eluf(s);
    __syncthreads();
    if(t<10){
        float l=fb2[t];
        for(int i=0;i<128;i++) l+=h[i]*fw2[t*128+i];
        lg[t]=l;
    }
    __syncthreads();
    if(t==0){
        float m=lg[0];
        for(int i=1;i<10;i++) m=fmaxf(m,lg[i]);
        float ss=0.f;
        for(int i=0;i<10;i++) ss+=expf(lg[i]-m);
        lse=m+logf(ss);
    }
    __syncthreads();
    if(t<10) out[g*10+t]=lg[t]-lse;
}

// ---------------- launch ----------------
extern "C" void kernel_launch(void* const* d_in, const int* in_sizes, int n_in,
                              void* d_out, int out_size){
    const float* x   =(const float*)d_in[0];
    const float* pos =(const float*)d_in[1];
    const int*   src =(const int*)  d_in[2];
    const int*   dst =(const int*)  d_in[3];
    const float* W1  =(const float*)d_in[4];
    const float* r1  =(const float*)d_in[5];
    const float* b1  =(const float*)d_in[6];
    const float* W2  =(const float*)d_in[7];
    const float* r2  =(const float*)d_in[8];
    const float* b2  =(const float*)d_in[9];
    const float* W3  =(const float*)d_in[10];
    const float* r3  =(const float*)d_in[11];
    const float* b3  =(const float*)d_in[12];
    const float* fw1 =(const float*)d_in[13];
    const float* fb1 =(const float*)d_in[14];
    const float* fw2 =(const float*)d_in[15];
    const float* fb2 =(const float*)d_in[16];
    float* out=(float*)d_out;

    float *pA2,*pX2,*pD2,*pX2o,*pA3,*pX3,*pD3,*pX3o;
    cudaGetSymbolAddress((void**)&pA2,  g_acc2);
    cudaGetSymbolAddress((void**)&pX2,  g_x2);
    cudaGetSymbolAddress((void**)&pD2,  g_deg2);
    cudaGetSymbolAddress((void**)&pX2o, g_x2o);
    cudaGetSymbolAddress((void**)&pA3,  g_acc3);
    cudaGetSymbolAddress((void**)&pX3,  g_x3);
    cudaGetSymbolAddress((void**)&pD3,  g_deg3);
    cudaGetSymbolAddress((void**)&pX3o, g_x3o);

    k_reset<<<2048,256>>>();
    k_amax0g<<<BB,256>>>(pos,src,dst);
    k_stage1<<<BB,256>>>(x,pos,src,dst,W1,r1,b1);
    k_dedup1g<<<BB,256>>>(src,dst);
    k_scatter2<<<(BB*EPG*8)/256,256>>>();
    k_convT<800,32><<<S1C/128,256>>>(pA2,pX2,pD2,W2,r2,b2,pX2o);
    k_pool2g<<<BB,256>>>();
    k_dedup2g<<<BB,256>>>();
    k_scatter3<<<(BB*EPG*16)/256,256>>>();
    k_convT<1600,64><<<S2C/128,256>>>(pA3,pX3,pD3,W3,r3,b3,pX3o);
    k_headg<<<BB,128>>>(fw1,fb1,fw2,fb2,out);
}

// round 5
// speedup vs baseline: 2.5812x; 1.0876x over previous
#include <cuda_runtime.h>

#define NN   76800
#define EE   1425408
#define BB   1024
#define EPG  1392
#define S1C  36864
#define S2C  25600

// ---------------- device scratch ----------------
__device__ float g_x2[S1C*32];
__device__ float g_cnt1[S1C];
__device__ float g_ppos1[S1C*2];
__device__ unsigned char g_cl1[NN];
__device__ unsigned g_el1[EE];
__device__ int   g_ecnt1[BB];
__device__ float g_deg2[S1C];
__device__ float g_acc2[25*S1C*32];
__device__ float g_x2o[S1C*64];
__device__ unsigned char g_cl2[S1C];
__device__ float g_x3[S2C*64];
__device__ float g_cnt2[S2C];
__device__ float g_ppos2[S2C*2];
__device__ unsigned g_el2[EE];
__device__ int   g_ecnt2[BB];
__device__ float g_deg3[S2C];
__device__ float g_acc3[25*S2C*64];
__device__ float g_x3o[S2C*64];
__device__ unsigned g_amax[4];

// ---------------- helpers ----------------
__device__ __forceinline__ unsigned encf(float f){
    unsigned u=__float_as_uint(f);
    return (u&0x80000000u)? ~u : (u|0x80000000u);
}
__device__ __forceinline__ float decf(unsigned u){
    return (u&0x80000000u)? __uint_as_float(u&0x7FFFFFFFu) : __uint_as_float(~u);
}
__device__ __forceinline__ float eluf(float x){ return x>0.f ? x : expm1f(x); }

__device__ __forceinline__ void redMaxU(unsigned* p, unsigned v){
    asm volatile("red.global.max.u32 [%0], %1;" :: "l"(p), "r"(v) : "memory");
}
__device__ __forceinline__ unsigned tf32c(float f){
    unsigned r; asm("cvt.rna.tf32.f32 %0, %1;" : "=r"(r) : "f"(f)); return r;
}
__device__ __forceinline__ void mma_tf32(float* d, unsigned a0,unsigned a1,unsigned a2,unsigned a3,
                                         unsigned b0, unsigned b1){
    asm("mma.sync.aligned.m16n8k8.row.col.f32.tf32.tf32.f32 "
        "{%0,%1,%2,%3}, {%4,%5,%6,%7}, {%8,%9}, {%0,%1,%2,%3};"
        : "+f"(d[0]),"+f"(d[1]),"+f"(d[2]),"+f"(d[3])
        : "r"(a0),"r"(a1),"r"(a2),"r"(a3),"r"(b0),"r"(b1));
}

// ---------------- tiny reset (amax only) ----------------
__global__ void k_reset0(){ if(threadIdx.x<4) g_amax[threadIdx.x]=0u; }

// ---------------- stage-1 global amax ----------------
__global__ void k_amax0g(const float* __restrict__ pos, const int* __restrict__ src,
                         const int* __restrict__ dst){
    int g=blockIdx.x, t=threadIdx.x;
    __shared__ unsigned wm[8];
    unsigned cand=0u;
    for(int i=t;i<EPG;i+=256){
        int e=g*EPG+i;
        int s=src[e], d=dst[e];
        float c0=fabsf(pos[2*s]-pos[2*d]);
        float c1=fabsf(pos[2*s+1]-pos[2*d+1]);
        cand=max(cand,__float_as_uint(fmaxf(c0,c1)));
    }
    unsigned m=__reduce_max_sync(0xffffffffu,cand);
    if((t&31)==0) wm[t>>5]=m;
    __syncthreads();
    if(t==0){
        unsigned mm=0;
        #pragma unroll
        for(int i=0;i<8;i++) mm=max(mm,wm[i]);
        redMaxU(&g_amax[0],mm);
    }
}

// ---------------- fused stage 1: scatter + conv1 + pool1 (one block per graph) ----------------
__global__ __launch_bounds__(256) void k_stage1(const float* __restrict__ x,
        const float* __restrict__ pos, const int* __restrict__ src,
        const int* __restrict__ dst, const float* __restrict__ W1,
        const float* __restrict__ r1, const float* __restrict__ b1){
    int g=blockIdx.x, t=threadIdx.x;
    __shared__ float acc[75*25];
    __shared__ float deg[75];
    __shared__ float posx[75], posy[75], xin[75];
    __shared__ float W1s[800], r1s[32], b1s[32];
    __shared__ float x1s[75*32];
    __shared__ unsigned px[36*32];
    __shared__ float cnt[36], psx[36], psy[36];
    __shared__ unsigned char cl[75];

    for(int i=t;i<1875;i+=256) acc[i]=0.f;
    for(int i=t;i<800;i+=256) W1s[i]=W1[i];
    if(t<75){
        deg[t]=0.f;
        float2 p=*(const float2*)&pos[(g*75+t)*2];
        posx[t]=p.x; posy[t]=p.y;
        xin[t]=x[g*75+t];
    }
    if(t>=96 && t<128){ r1s[t-96]=r1[t-96]; b1s[t-96]=b1[t-96]; }
    if(t>=128 && t<164){ int c=t-128; cnt[c]=0.f; psx[c]=0.f; psy[c]=0.f; }
    for(int i=t;i<1152;i+=256) px[i]=encf(-1e30f);
    __syncthreads();
    if(t<75){
        int c0=min(max((int)floorf(posx[t]/5.f),0),5);
        int c1=min(max((int)floorf(posy[t]/5.f),0),5);
        int c=c1*6+c0;
        cl[t]=(unsigned char)c;
        atomicAdd(&cnt[c],1.f);
        atomicAdd(&psx[c],posx[t]);
        atomicAdd(&psy[c],posy[t]);
    }
    float amax=fmaxf(__uint_as_float(g_amax[0]),1e-12f);
    float inv=0.5f/amax;
    for(int i=t;i<EPG;i+=256){
        int e=g*EPG+i;
        int s=src[e]-g*75, d=dst[e]-g*75;
        float p0=(posx[s]-posx[d])*inv+0.5f;
        float p1=(posy[s]-posy[d])*inv+0.5f;
        float v0=fminf(fmaxf(p0,0.f),1.f)*4.f;
        float v1=fminf(fmaxf(p1,0.f),1.f)*4.f;
        float b0=fminf(floorf(v0),3.f), b1f=fminf(floorf(v1),3.f);
        int i0=(int)b0, i1=(int)b1f;
        float f0=v0-b0, f1=v1-b1f;
        float xs=xin[s];
        float* base=&acc[d*25+i0+5*i1];
        atomicAdd(base,   (1.f-f0)*(1.f-f1)*xs);
        atomicAdd(base+1, f0*(1.f-f1)*xs);
        atomicAdd(base+5, (1.f-f0)*f1*xs);
        atomicAdd(base+6, f0*f1*xs);
        atomicAdd(&deg[d],1.f);
    }
    __syncthreads();
    for(int i=t;i<2400;i+=256){
        int n=i>>5, o=i&31;
        const float* ar=&acc[n*25];
        float s=0.f;
#pragma unroll
        for(int k=0;k<25;k++) s+=ar[k]*W1s[k*32+o];
        s=s/fmaxf(deg[n],1.f)+xin[n]*r1s[o]+b1s[o];
        x1s[i]=eluf(s);
    }
    __syncthreads();
    for(int i=t;i<2400;i+=256){
        int n=i>>5, f=i&31;
        atomicMax(&px[cl[n]*32+f], encf(x1s[i]));
    }
    __syncthreads();
    for(int i=t;i<1152;i+=256){
        int s=i>>5, f=i&31;
        float c=cnt[s];
        g_x2[(g*36+s)*32+f]=(c>0.f)? decf(px[i]) : 0.f;
        if(f==0){
            g_cnt1[g*36+s]=c;
            float ic=1.f/fmaxf(c,1.f);
            g_ppos1[(g*36+s)*2]=psx[s]*ic;
            g_ppos1[(g*36+s)*2+1]=psy[s]*ic;
        }
    }
    if(t<75) g_cl1[g*75+t]=cl[t];
}

// ---------------- dedup1 (per graph, smem bitmask) -> compact list ----------------
__global__ void k_dedup1g(const int* __restrict__ src, const int* __restrict__ dst){
    int g=blockIdx.x, t=threadIdx.x;
    __shared__ unsigned bm[41];
    __shared__ float deg[36], ppx[36], ppy[36];
    __shared__ unsigned char cl[75];
    __shared__ int cnt;
    __shared__ unsigned cmax;
    if(t<41) bm[t]=0u;
    if(t<36){ deg[t]=0.f; ppx[t]=g_ppos1[(g*36+t)*2]; ppy[t]=g_ppos1[(g*36+t)*2+1]; }
    if(t<75) cl[t]=g_cl1[g*75+t];
    if(t==0){ cnt=0; cmax=0u; }
    __syncthreads();
    for(int i=t;i<EPG;i+=256){
        int e=g*EPG+i;
        int a=cl[src[e]-g*75], b=cl[dst[e]-g*75];
        if(a!=b){
            int key=a*36+b;
            unsigned bit=1u<<(key&31);
            if(!(atomicOr(&bm[key>>5],bit)&bit)){
                int idx=atomicAdd(&cnt,1);
                g_el1[g*EPG+idx]=(unsigned)a|((unsigned)b<<8);
                atomicAdd(&deg[b],1.f);
                float c0=fabsf(ppx[a]-ppx[b]), c1=fabsf(ppy[a]-ppy[b]);
                atomicMax(&cmax,__float_as_uint(fmaxf(c0,c1)));
            }
        }
    }
    __syncthreads();
    if(t<36) g_deg2[g*36+t]=deg[t];
    if(t==0){ g_ecnt1[g]=cnt; redMaxU(&g_amax[1],cmax); }
}

// ---------------- stage-2 CSR gather: per-graph counting sort + plain stores ----------------
// bins = dst(36) x kslot(25) = 900. acc2[(g*900+b)*32+f] = (1/deg)*sum entries.
__global__ __launch_bounds__(256) void k_gather2(){
    int g=blockIdx.x, t=threadIdx.x, lane=t&31, w=t>>5;
    __shared__ float xs[36*32];
    __shared__ float ppx[36], ppy[36], invd[36];
    __shared__ int cnt[901], offs[901], cursor[900];
    __shared__ int tsum[256];
    __shared__ float sw_[5056];
    __shared__ unsigned char sa_[5056];
    int ec=g_ecnt1[g];
    for(int i=t;i<36*32;i+=256) xs[i]=g_x2[g*36*32+i];
    if(t<36){
        ppx[t]=g_ppos1[(g*36+t)*2]; ppy[t]=g_ppos1[(g*36+t)*2+1];
        invd[t]=1.f/fmaxf(g_deg2[g*36+t],1.f);
    }
    for(int i=t;i<901;i+=256) cnt[i]=0;
    __syncthreads();
    float amax=fmaxf(__uint_as_float(g_amax[1]),1e-12f);
    float inv=0.5f/amax;
    // pass 1: counts
    for(int i=t;i<ec;i+=256){
        unsigned r=g_el1[g*EPG+i];
        int a=r&255, b=(r>>8)&255;
        float p0=(ppx[a]-ppx[b])*inv+0.5f;
        float p1=(ppy[a]-ppy[b])*inv+0.5f;
        float v0=fminf(fmaxf(p0,0.f),1.f)*4.f;
        float v1=fminf(fmaxf(p1,0.f),1.f)*4.f;
        int i0=(int)fminf(floorf(v0),3.f), i1=(int)fminf(floorf(v1),3.f);
        int base=b*25+i0+5*i1;
        atomicAdd(&cnt[base],1); atomicAdd(&cnt[base+1],1);
        atomicAdd(&cnt[base+5],1); atomicAdd(&cnt[base+6],1);
    }
    __syncthreads();
    // exclusive scan cnt[0..900) -> offs, offs[900]=total
    {
        int c0=t*4, c1=min(900,c0+4);
        int s=0;
        for(int i=c0;i<c1;i++) s+=cnt[i];
        tsum[t]=s;
        __syncthreads();
        for(int d=1;d<256;d<<=1){
            int v=(t>=d)? tsum[t-d]:0;
            __syncthreads();
            tsum[t]+=v;
            __syncthreads();
        }
        int base=(t==0)?0:tsum[t-1];
        for(int i=c0;i<c1;i++){ int v=cnt[i]; offs[i]=base; base+=v; }
        if(t==255) offs[900]=base;
    }
    __syncthreads();
    for(int i=t;i<900;i+=256) cursor[i]=offs[i];
    __syncthreads();
    // pass 2: fill sorted entries
    for(int i=t;i<ec;i+=256){
        unsigned r=g_el1[g*EPG+i];
        int a=r&255, b=(r>>8)&255;
        float p0=(ppx[a]-ppx[b])*inv+0.5f;
        float p1=(ppy[a]-ppy[b])*inv+0.5f;
        float v0=fminf(fmaxf(p0,0.f),1.f)*4.f;
        float v1=fminf(fmaxf(p1,0.f),1.f)*4.f;
        float b0=fminf(floorf(v0),3.f), b1f=fminf(floorf(v1),3.f);
        int i0=(int)b0, i1=(int)b1f;
        float f0=v0-b0, f1=v1-b1f;
        int base=b*25+i0+5*i1;
        int j;
        j=atomicAdd(&cursor[base],1);   sw_[j]=(1.f-f0)*(1.f-f1); sa_[j]=(unsigned char)a;
        j=atomicAdd(&cursor[base+1],1); sw_[j]=f0*(1.f-f1);       sa_[j]=(unsigned char)a;
        j=atomicAdd(&cursor[base+5],1); sw_[j]=(1.f-f0)*f1;       sa_[j]=(unsigned char)a;
        j=atomicAdd(&cursor[base+6],1); sw_[j]=f0*f1;             sa_[j]=(unsigned char)a;
    }
    __syncthreads();
    // gather: warp per bin, lane = feature; plain coalesced stores (no reset needed)
    for(int b=w;b<900;b+=8){
        int s0=offs[b], s1=offs[b+1];
        float acc=0.f;
        for(int j=s0;j<s1;j++) acc+=sw_[j]*xs[sa_[j]*32+lane];
        g_acc2[(size_t)(g*900+b)*32+lane]=acc*invd[b/25];
    }
}

// ---------------- tf32 tensor-core conv GEMM (prefetch, deg pre-folded) ----------------
// out = elu(A@W + X@R + b). Tile M=128, N=64, K-tile=32. 256 thr (8 warps).
template<int KK,int FIN>
__global__ __launch_bounds__(256) void k_convT(
    const float* __restrict__ A, const float* __restrict__ Xin,
    const float* __restrict__ W, const float* __restrict__ R,
    const float* __restrict__ Bv, float* __restrict__ Out)
{
    constexpr int nTA=KK/32, nT=nTA+FIN/32;
    __shared__ unsigned As[32][136];
    __shared__ __align__(16) unsigned Ws[32][72];
    int t=threadIdx.x, lane=t&31, w=t>>5;
    int gid=lane>>2, tig=lane&3;
    int n0=blockIdx.x*128;
    int r0=n0+w*16+gid;
    float C[8][4];
#pragma unroll
    for(int j=0;j<8;j++){ C[j][0]=0.f; C[j][1]=0.f; C[j][2]=0.f; C[j][3]=0.f; }
    int ar=t>>1, acb=(t&1)*16;
    int wr=t>>3, wcb=(t&7)*8;
    float4 pa0,pa1,pa2,pa3,pw0,pw1;
    auto loadT=[&](int j){
        const float *Ap, *Wp;
        if(j<nTA){ Ap=A+(size_t)(n0+ar)*KK+j*32+acb;
                   Wp=W+(size_t)(j*32+wr)*64+wcb; }
        else     { Ap=Xin+(size_t)(n0+ar)*FIN+(j-nTA)*32+acb;
                   Wp=R+(size_t)((j-nTA)*32+wr)*64+wcb; }
        pa0=*(const float4*)Ap;     pa1=*(const float4*)(Ap+4);
        pa2=*(const float4*)(Ap+8); pa3=*(const float4*)(Ap+12);
        pw0=*(const float4*)Wp;     pw1=*(const float4*)(Wp+4);
    };
    loadT(0);
    for(int j=0;j<nT;j++){
        __syncthreads();
        As[acb+ 0][ar]=tf32c(pa0.x); As[acb+ 1][ar]=tf32c(pa0.y);
        As[acb+ 2][ar]=tf32c(pa0.z); As[acb+ 3][ar]=tf32c(pa0.w);
        As[acb+ 4][ar]=tf32c(pa1.x); As[acb+ 5][ar]=tf32c(pa1.y);
        As[acb+ 6][ar]=tf32c(pa1.z); As[acb+ 7][ar]=tf32c(pa1.w);
        As[acb+ 8][ar]=tf32c(pa2.x); As[acb+ 9][ar]=tf32c(pa2.y);
        As[acb+10][ar]=tf32c(pa2.z); As[acb+11][ar]=tf32c(pa2.w);
        As[acb+12][ar]=tf32c(pa3.x); As[acb+13][ar]=tf32c(pa3.y);
        As[acb+14][ar]=tf32c(pa3.z); As[acb+15][ar]=tf32c(pa3.w);
        uint4 wv;
        wv.x=tf32c(pw0.x); wv.y=tf32c(pw0.y); wv.z=tf32c(pw0.z); wv.w=tf32c(pw0.w);
        *(uint4*)&Ws[wr][wcb]=wv;
        wv.x=tf32c(pw1.x); wv.y=tf32c(pw1.y); wv.z=tf32c(pw1.z); wv.w=tf32c(pw1.w);
        *(uint4*)&Ws[wr][wcb+4]=wv;
        __syncthreads();
        if(j+1<nT) loadT(j+1);
#pragma unroll
        for(int k8=0;k8<32;k8+=8){
            unsigned a0=As[k8+tig  ][w*16+gid];
            unsigned a1=As[k8+tig  ][w*16+8+gid];
            unsigned a2=As[k8+tig+4][w*16+gid];
            unsigned a3=As[k8+tig+4][w*16+8+gid];
#pragma unroll
            for(int jj=0;jj<8;jj++){
                unsigned b0=Ws[k8+tig  ][jj*8+gid];
                unsigned b1=Ws[k8+tig+4][jj*8+gid];
                mma_tf32(C[jj],a0,a1,a2,a3,b0,b1);
            }
        }
    }
#pragma unroll
    for(int jj=0;jj<8;jj++){
        int c=jj*8+2*tig;
        float bv0=Bv[c], bv1=Bv[c+1];
        float2 o;
        o.x=eluf(C[jj][0]+bv0); o.y=eluf(C[jj][1]+bv1);
        *(float2*)&Out[(size_t)r0*64+c]=o;
        o.x=eluf(C[jj][2]+bv0); o.y=eluf(C[jj][3]+bv1);
        *(float2*)&Out[(size_t)(r0+8)*64+c]=o;
    }
}

// ---------------- pool2 + fin2 fused (per graph) ----------------
__global__ void k_pool2g(){
    int g=blockIdx.x, t=threadIdx.x;
    __shared__ unsigned px[25*64];
    __shared__ float cnt[25], psx[25], psy[25];
    __shared__ unsigned char cl[36], vld[36];
    for(int i=t;i<25*64;i+=256) px[i]=encf(-1e30f);
    if(t<25){ cnt[t]=0.f; psx[t]=0.f; psy[t]=0.f; }
    __syncthreads();
    if(t<36){
        float qx=g_ppos1[(g*36+t)*2], qy=g_ppos1[(g*36+t)*2+1];
        int c0=min(max((int)floorf(qx/7.f),0),4);
        int c1=min(max((int)floorf(qy/7.f),0),4);
        int c=c1*5+c0;
        cl[t]=(unsigned char)c;
        g_cl2[g*36+t]=(unsigned char)c;
        unsigned char v=(g_cnt1[g*36+t]>0.f)?1:0;
        vld[t]=v;
        if(v){ atomicAdd(&cnt[c],1.f); atomicAdd(&psx[c],qx); atomicAdd(&psy[c],qy); }
    }
    __syncthreads();
    for(int i=t;i<36*64;i+=256){
        int s=i>>6, f=i&63;
        if(vld[s]) atomicMax(&px[cl[s]*64+f], encf(g_x2o[(g*36+s)*64+f]));
    }
    __syncthreads();
    for(int i=t;i<25*64;i+=256){
        int s=i>>6, f=i&63;
        float c=cnt[s];
        g_x3[(g*25+s)*64+f]=(c>0.f)? decf(px[i]) : 0.f;
        if(f==0){
            g_cnt2[g*25+s]=c;
            float ic=1.f/fmaxf(c,1.f);
            g_ppos2[(g*25+s)*2]=psx[s]*ic;
            g_ppos2[(g*25+s)*2+1]=psy[s]*ic;
        }
    }
}

// ---------------- dedup2 (per graph) ----------------
__global__ void k_dedup2g(){
    int g=blockIdx.x, t=threadIdx.x;
    __shared__ unsigned bm[20];
    __shared__ float deg[25], ppx[25], ppy[25];
    __shared__ unsigned char cl[36];
    __shared__ int cnt;
    __shared__ unsigned cmax;
    if(t<20) bm[t]=0u;
    if(t<25){ deg[t]=0.f; ppx[t]=g_ppos2[(g*25+t)*2]; ppy[t]=g_ppos2[(g*25+t)*2+1]; }
    if(t<36) cl[t]=g_cl2[g*36+t];
    if(t==0){ cnt=0; cmax=0u; }
    __syncthreads();
    int ec=g_ecnt1[g];
    for(int i=t;i<ec;i+=256){
        unsigned r=g_el1[g*EPG+i];
        int a=cl[r&255], b=cl[(r>>8)&255];
        if(a!=b){
            int key=a*25+b;
            unsigned bit=1u<<(key&31);
            if(!(atomicOr(&bm[key>>5],bit)&bit)){
                int idx=atomicAdd(&cnt,1);
                g_el2[g*EPG+idx]=(unsigned)a|((unsigned)b<<8);
                atomicAdd(&deg[b],1.f);
                float c0=fabsf(ppx[a]-ppx[b]), c1=fabsf(ppy[a]-ppy[b]);
                atomicMax(&cmax,__float_as_uint(fmaxf(c0,c1)));
            }
        }
    }
    __syncthreads();
    if(t<25) g_deg3[g*25+t]=deg[t];
    if(t==0){ g_ecnt2[g]=cnt; redMaxU(&g_amax[2],cmax); }
}

// ---------------- stage-3 CSR gather: bins = dst(25) x kslot(25) = 625 ----------------
__global__ __launch_bounds__(256) void k_gather3(){
    int g=blockIdx.x, t=threadIdx.x, lane=t&31, w=t>>5;
    __shared__ float xs[25*64];
    __shared__ float ppx[25], ppy[25], invd[25];
    __shared__ int cnt[626], offs[626], cursor[625];
    __shared__ int tsum[256];
    __shared__ float sw_[2432];
    __shared__ unsigned char sa_[2432];
    int ec=g_ecnt2[g];
    for(int i=t;i<25*64;i+=256) xs[i]=g_x3[g*25*64+i];
    if(t<25){
        ppx[t]=g_ppos2[(g*25+t)*2]; ppy[t]=g_ppos2[(g*25+t)*2+1];
        invd[t]=1.f/fmaxf(g_deg3[g*25+t],1.f);
    }
    for(int i=t;i<626;i+=256) cnt[i]=0;
    __syncthreads();
    float amax=fmaxf(__uint_as_float(g_amax[2]),1e-12f);
    float inv=0.5f/amax;
    for(int i=t;i<ec;i+=256){
        unsigned r=g_el2[g*EPG+i];
        int a=r&255, b=(r>>8)&255;
        float p0=(ppx[a]-ppx[b])*inv+0.5f;
        float p1=(ppy[a]-ppy[b])*inv+0.5f;
        float v0=fminf(fmaxf(p0,0.f),1.f)*4.f;
        float v1=fminf(fmaxf(p1,0.f),1.f)*4.f;
        int i0=(int)fminf(floorf(v0),3.f), i1=(int)fminf(floorf(v1),3.f);
        int base=b*25+i0+5*i1;
        atomicAdd(&cnt[base],1); atomicAdd(&cnt[base+1],1);
        atomicAdd(&cnt[base+5],1); atomicAdd(&cnt[base+6],1);
    }
    __syncthreads();
    {
        int c0=t*3, c1=min(625,c0+3);
        int s=0;
        for(int i=c0;i<c1;i++) s+=cnt[i];
        tsum[t]=s;
        __syncthreads();
        for(int d=1;d<256;d<<=1){
            int v=(t>=d)? tsum[t-d]:0;
            __syncthreads();
            tsum[t]+=v;
            __syncthreads();
        }
        int base=(t==0)?0:tsum[t-1];
        for(int i=c0;i<c1;i++){ int v=cnt[i]; offs[i]=base; base+=v; }
        if(t==255) offs[625]=base;
    }
    __syncthreads();
    for(int i=t;i<625;i+=256) cursor[i]=offs[i];
    __syncthreads();
    for(int i=t;i<ec;i+=256){
        unsigned r=g_el2[g*EPG+i];
        int a=r&255, b=(r>>8)&255;
        float p0=(ppx[a]-ppx[b])*inv+0.5f;
        float p1=(ppy[a]-ppy[b])*inv+0.5f;
        float v0=fminf(fmaxf(p0,0.f),1.f)*4.f;
        float v1=fminf(fmaxf(p1,0.f),1.f)*4.f;
        float b0=fminf(floorf(v0),3.f), b1f=fminf(floorf(v1),3.f);
        int i0=(int)b0, i1=(int)b1f;
        float f0=v0-b0, f1=v1-b1f;
        int base=b*25+i0+5*i1;
        int j;
        j=atomicAdd(&cursor[base],1);   sw_[j]=(1.f-f0)*(1.f-f1); sa_[j]=(unsigned char)a;
        j=atomicAdd(&cursor[base+1],1); sw_[j]=f0*(1.f-f1);       sa_[j]=(unsigned char)a;
        j=atomicAdd(&cursor[base+5],1); sw_[j]=(1.f-f0)*f1;       sa_[j]=(unsigned char)a;
        j=atomicAdd(&cursor[base+6],1); sw_[j]=f0*f1;             sa_[j]=(unsigned char)a;
    }
    __syncthreads();
    for(int b=w;b<625;b+=8){
        int s0=offs[b], s1=offs[b+1];
        float a0=0.f, a1=0.f;
        for(int j=s0;j<s1;j++){
            float wt=sw_[j]; int a=sa_[j];
            a0+=wt*xs[a*64+lane];
            a1+=wt*xs[a*64+32+lane];
        }
        float iv=invd[b/25];
        g_acc3[(size_t)(g*625+b)*64+lane]=a0*iv;
        g_acc3[(size_t)(g*625+b)*64+32+lane]=a1*iv;
    }
}

// ---------------- fused final pool + FC head (per graph) ----------------
__global__ __launch_bounds__(128) void k_headg(const float* __restrict__ fw1,
        const float* __restrict__ fb1, const float* __restrict__ fw2,
        const float* __restrict__ fb2, float* __restrict__ out){
    __shared__ unsigned enc4[4*64];
    __shared__ unsigned any[4];
    __shared__ float in[256];
    __shared__ float h[128];
    __shared__ float lg[10];
    __shared__ float lse;
    int g=blockIdx.x, t=threadIdx.x;
    for(int i=t;i<256;i+=128) enc4[i]=encf(-1e30f);
    if(t<4) any[t]=0u;
    __syncthreads();
    for(int i=t;i<25*64;i+=128){
        int n=i>>6, f=i&63;
        if(g_cnt2[g*25+n]>0.f){
            float qx=g_ppos2[(g*25+n)*2], qy=g_ppos2[(g*25+n)*2+1];
            int c0=min(max((int)floorf(qx/14.f),0),1);
            int c1=min(max((int)floorf(qy/14.f),0),1);
            int cell=c1*2+c0;
            atomicMax(&enc4[cell*64+f], encf(g_x3o[(g*25+n)*64+f]));
            if(f==0) atomicOr(&any[cell],1u);
        }
    }
    __syncthreads();
    for(int i=t;i<256;i+=128)
        in[i]=any[i>>6]? decf(enc4[i]) : 0.f;
    __syncthreads();
    float s=fb1[t];
    const float4* wr=(const float4*)(fw1+(size_t)t*256);
#pragma unroll 8
    for(int i=0;i<64;i++){
        float4 w=wr[i];
        const float4 v=*(const float4*)&in[i*4];
        s+=w.x*v.x+w.y*v.y+w.z*v.z+w.w*v.w;
    }
    h[t]=eluf(s);
    __syncthreads();
    if(t<10){
        float l=fb2[t];
        for(int i=0;i<128;i++) l+=h[i]*fw2[t*128+i];
        lg[t]=l;
    }
    __syncthreads();
    if(t==0){
        float m=lg[0];
        for(int i=1;i<10;i++) m=fmaxf(m,lg[i]);
        float ss=0.f;
        for(int i=0;i<10;i++) ss+=expf(lg[i]-m);
        lse=m+logf(ss);
    }
    __syncthreads();
    if(t<10) out[g*10+t]=lg[t]-lse;
}

// ---------------- launch ----------------
extern "C" void kernel_launch(void* const* d_in, const int* in_sizes, int n_in,
                              void* d_out, int out_size){
    const float* x   =(const float*)d_in[0];
    const float* pos =(const float*)d_in[1];
    const int*   src =(const int*)  d_in[2];
    const int*   dst =(const int*)  d_in[3];
    const float* W1  =(const float*)d_in[4];
    const float* r1  =(const float*)d_in[5];
    const float* b1  =(const float*)d_in[6];
    const float* W2  =(const float*)d_in[7];
    const float* r2  =(const float*)d_in[8];
    const float* b2  =(const float*)d_in[9];
    const float* W3  =(const float*)d_in[10];
    const float* r3  =(const float*)d_in[11];
    const float* b3  =(const float*)d_in[12];
    const float* fw1 =(const float*)d_in[13];
    const float* fb1 =(const float*)d_in[14];
    const float* fw2 =(const float*)d_in[15];
    const float* fb2 =(const float*)d_in[16];
    float* out=(float*)d_out;

    float *pA2,*pX2,*pX2o,*pA3,*pX3,*pX3o;
    cudaGetSymbolAddress((void**)&pA2,  g_acc2);
    cudaGetSymbolAddress((void**)&pX2,  g_x2);
    cudaGetSymbolAddress((void**)&pX2o, g_x2o);
    cudaGetSymbolAddress((void**)&pA3,  g_acc3);
    cudaGetSymbolAddress((void**)&pX3,  g_x3);
    cudaGetSymbolAddress((void**)&pX3o, g_x3o);

    k_reset0<<<1,32>>>();
    k_amax0g<<<BB,256>>>(pos,src,dst);
    k_stage1<<<BB,256>>>(x,pos,src,dst,W1,r1,b1);
    k_dedup1g<<<BB,256>>>(src,dst);
    k_gather2<<<BB,256>>>();
    k_convT<800,32><<<S1C/128,256>>>(pA2,pX2,W2,r2,b2,pX2o);
    k_pool2g<<<BB,256>>>();
    k_dedup2g<<<BB,256>>>();
    k_gather3<<<BB,256>>>();
    k_convT<1600,64><<<S2C/128,256>>>(pA3,pX3,W3,r3,b3,pX3o);
    k_headg<<<BB,128>>>(fw1,fb1,fw2,fb2,out);
}

// round 6
// speedup vs baseline: 3.2143x; 1.2453x over previous
#include <cuda_runtime.h>
#include <cuda_bf16.h>

#define NN   76800
#define EE   1425408
#define BB   1024
#define EPG  1392
#define S1C  36864
#define S2C  25600

// ---------------- device scratch ----------------
__device__ float g_x2[S1C*32];
__device__ __nv_bfloat16 g_x2h[S1C*32];
__device__ float g_cnt1[S1C];
__device__ float g_ppos1[S1C*2];
__device__ unsigned g_el1[EE];
__device__ int   g_ecnt1[BB];
__device__ float g_deg2[S1C];
__device__ __nv_bfloat16 g_acc2h[S1C*25*32];
__device__ float g_x2o[S1C*64];
__device__ float g_x3[S2C*64];
__device__ __nv_bfloat16 g_x3h[S2C*64];
__device__ float g_cnt2[S2C];
__device__ float g_ppos2[S2C*2];
__device__ unsigned g_el2[EE];
__device__ int   g_ecnt2[BB];
__device__ float g_deg3[S2C];
__device__ __nv_bfloat16 g_acc3h[S2C*25*64];
__device__ float g_x3o[S2C*64];
__device__ unsigned g_amax[4];
__device__ unsigned g_Wp2[416*64];   // bf16x2-packed [W2;r2], K'=832 -> 416 kp rows
__device__ unsigned g_Wp3[832*64];   // bf16x2-packed [W3;r3], K'=1664 -> 832 kp rows

// ---------------- helpers ----------------
__device__ __forceinline__ unsigned encf(float f){
    unsigned u=__float_as_uint(f);
    return (u&0x80000000u)? ~u : (u|0x80000000u);
}
__device__ __forceinline__ float decf(unsigned u){
    return (u&0x80000000u)? __uint_as_float(u&0x7FFFFFFFu) : __uint_as_float(~u);
}
__device__ __forceinline__ float eluf(float x){ return x>0.f ? x : expm1f(x); }
__device__ __forceinline__ void redMaxU(unsigned* p, unsigned v){
    asm volatile("red.global.max.u32 [%0], %1;" :: "l"(p), "r"(v) : "memory");
}
__device__ __forceinline__ unsigned packbf(float a, float b){
    __nv_bfloat162 h=__floats2bfloat162_rn(a,b);
    return *reinterpret_cast<unsigned*>(&h);
}
__device__ __forceinline__ void mma_bf16(float* d, unsigned a0,unsigned a1,unsigned a2,unsigned a3,
                                         unsigned b0, unsigned b1){
    asm("mma.sync.aligned.m16n8k16.row.col.f32.bf16.bf16.f32 "
        "{%0,%1,%2,%3}, {%4,%5,%6,%7}, {%8,%9}, {%0,%1,%2,%3};"
        : "+f"(d[0]),"+f"(d[1]),"+f"(d[2]),"+f"(d[3])
        : "r"(a0),"r"(a1),"r"(a2),"r"(a3),"r"(b0),"r"(b1));
}

// ---------------- tiny reset ----------------
__global__ void k_reset0(){ if(threadIdx.x<4) g_amax[threadIdx.x]=0u; }

// ---------------- pack weights+roots to bf16 pairs ----------------
__global__ void k_prepW(const float* __restrict__ W2, const float* __restrict__ r2,
                        const float* __restrict__ W3, const float* __restrict__ r3){
    int i=blockIdx.x*blockDim.x+threadIdx.x;
    if(i<416*64){
        int kp=i>>6, n=i&63;
        float lo,hi;
        if(kp<400){ lo=W2[(2*kp)*64+n]; hi=W2[(2*kp+1)*64+n]; }
        else      { int q=kp-400; lo=r2[(2*q)*64+n]; hi=r2[(2*q+1)*64+n]; }
        g_Wp2[i]=packbf(lo,hi);
    }
    int j=i-416*64;
    if(j>=0 && j<832*64){
        int kp=j>>6, n=j&63;
        float lo,hi;
        if(kp<800){ lo=W3[(2*kp)*64+n]; hi=W3[(2*kp+1)*64+n]; }
        else      { int q=kp-800; lo=r3[(2*q)*64+n]; hi=r3[(2*q+1)*64+n]; }
        g_Wp3[j]=packbf(lo,hi);
    }
}

// ---------------- stage-1 global amax ----------------
__global__ void k_amax0g(const float* __restrict__ pos, const int* __restrict__ src,
                         const int* __restrict__ dst){
    int g=blockIdx.x, t=threadIdx.x;
    __shared__ unsigned wm[8];
    unsigned cand=0u;
    for(int i=t;i<EPG;i+=256){
        int e=g*EPG+i;
        int s=src[e], d=dst[e];
        float c0=fabsf(pos[2*s]-pos[2*d]);
        float c1=fabsf(pos[2*s+1]-pos[2*d+1]);
        cand=max(cand,__float_as_uint(fmaxf(c0,c1)));
    }
    unsigned m=__reduce_max_sync(0xffffffffu,cand);
    if((t&31)==0) wm[t>>5]=m;
    __syncthreads();
    if(t==0){
        unsigned mm=0;
        #pragma unroll
        for(int i=0;i<8;i++) mm=max(mm,wm[i]);
        redMaxU(&g_amax[0],mm);
    }
}

// ---------------- fused stage 1: scatter + conv1 + pool1 + dedup1 ----------------
__global__ __launch_bounds__(256) void k_stage1(const float* __restrict__ x,
        const float* __restrict__ pos, const int* __restrict__ src,
        const int* __restrict__ dst, const float* __restrict__ W1,
        const float* __restrict__ r1, const float* __restrict__ b1){
    int g=blockIdx.x, t=threadIdx.x;
    __shared__ float acc[75*25];
    __shared__ float deg[75];
    __shared__ float posx[75], posy[75], xin[75];
    __shared__ float W1s[800], r1s[32], b1s[32];
    __shared__ float x1s[75*32];
    __shared__ unsigned px[36*32];
    __shared__ float cnt[36], psx[36], psy[36], ppx[36], ppy[36], deg2s[36];
    __shared__ unsigned char cl[75];
    __shared__ unsigned bm[41];
    __shared__ int ecnt;
    __shared__ unsigned cmax;

    for(int i=t;i<1875;i+=256) acc[i]=0.f;
    for(int i=t;i<800;i+=256) W1s[i]=W1[i];
    if(t<75){
        deg[t]=0.f;
        float2 p=*(const float2*)&pos[(g*75+t)*2];
        posx[t]=p.x; posy[t]=p.y;
        xin[t]=x[g*75+t];
    }
    if(t>=96 && t<128){ r1s[t-96]=r1[t-96]; b1s[t-96]=b1[t-96]; }
    if(t>=128 && t<164){ int c=t-128; cnt[c]=0.f; psx[c]=0.f; psy[c]=0.f; deg2s[c]=0.f; }
    if(t>=164 && t<205) bm[t-164]=0u;
    if(t==0){ ecnt=0; cmax=0u; }
    for(int i=t;i<1152;i+=256) px[i]=encf(-1e30f);
    __syncthreads();
    if(t<75){
        int c0=min(max((int)floorf(posx[t]/5.f),0),5);
        int c1=min(max((int)floorf(posy[t]/5.f),0),5);
        int c=c1*6+c0;
        cl[t]=(unsigned char)c;
        atomicAdd(&cnt[c],1.f);
        atomicAdd(&psx[c],posx[t]);
        atomicAdd(&psy[c],posy[t]);
    }
    __syncthreads();
    if(t<36){
        float ic=1.f/fmaxf(cnt[t],1.f);
        ppx[t]=psx[t]*ic; ppy[t]=psy[t]*ic;
    }
    __syncthreads();
    float amax=fmaxf(__uint_as_float(g_amax[0]),1e-12f);
    float inv=0.5f/amax;
    for(int i=t;i<EPG;i+=256){
        int e=g*EPG+i;
        int s=src[e]-g*75, d=dst[e]-g*75;
        float p0=(posx[s]-posx[d])*inv+0.5f;
        float p1=(posy[s]-posy[d])*inv+0.5f;
        float v0=fminf(fmaxf(p0,0.f),1.f)*4.f;
        float v1=fminf(fmaxf(p1,0.f),1.f)*4.f;
        float b0=fminf(floorf(v0),3.f), b1f=fminf(floorf(v1),3.f);
        int i0=(int)b0, i1=(int)b1f;
        float f0=v0-b0, f1=v1-b1f;
        float xs=xin[s];
        float* base=&acc[d*25+i0+5*i1];
        atomicAdd(base,   (1.f-f0)*(1.f-f1)*xs);
        atomicAdd(base+1, f0*(1.f-f1)*xs);
        atomicAdd(base+5, (1.f-f0)*f1*xs);
        atomicAdd(base+6, f0*f1*xs);
        atomicAdd(&deg[d],1.f);
        // dedup for pool1 graph (fused)
        int a=cl[s], b=cl[d];
        if(a!=b){
            int key=a*36+b;
            unsigned bit=1u<<(key&31);
            if(!(atomicOr(&bm[key>>5],bit)&bit)){
                int idx=atomicAdd(&ecnt,1);
                g_el1[g*EPG+idx]=(unsigned)a|((unsigned)b<<8);
                atomicAdd(&deg2s[b],1.f);
                float c0=fabsf(ppx[a]-ppx[b]), c1=fabsf(ppy[a]-ppy[b]);
                atomicMax(&cmax,__float_as_uint(fmaxf(c0,c1)));
            }
        }
    }
    __syncthreads();
    for(int i=t;i<2400;i+=256){
        int n=i>>5, o=i&31;
        const float* ar=&acc[n*25];
        float s=0.f;
#pragma unroll
        for(int k=0;k<25;k++) s+=ar[k]*W1s[k*32+o];
        s=s/fmaxf(deg[n],1.f)+xin[n]*r1s[o]+b1s[o];
        x1s[i]=eluf(s);
    }
    __syncthreads();
    for(int i=t;i<2400;i+=256){
        int n=i>>5, f=i&31;
        atomicMax(&px[cl[n]*32+f], encf(x1s[i]));
    }
    __syncthreads();
    for(int i=t;i<1152;i+=256){
        int s=i>>5, f=i&31;
        float c=cnt[s];
        float v=(c>0.f)? decf(px[i]) : 0.f;
        g_x2[(g*36+s)*32+f]=v;
        g_x2h[(g*36+s)*32+f]=__float2bfloat16(v);
        if(f==0){
            g_cnt1[g*36+s]=c;
            g_ppos1[(g*36+s)*2]=ppx[s];
            g_ppos1[(g*36+s)*2+1]=ppy[s];
            g_deg2[g*36+s]=deg2s[s];
        }
    }
    if(t==0){ g_ecnt1[g]=ecnt; redMaxU(&g_amax[1],cmax); }
}

// ---------------- stage-2 CSR gather -> bf16 acc ----------------
__global__ __launch_bounds__(256) void k_gather2(){
    int g=blockIdx.x, t=threadIdx.x, lane=t&31, w=t>>5;
    __shared__ float xs[36*32];
    __shared__ float ppx[36], ppy[36], invd[36];
    __shared__ int cnt[901], offs[901], cursor[900];
    __shared__ int tsum[256];
    __shared__ float sw_[5056];
    __shared__ unsigned char sa_[5056];
    int ec=g_ecnt1[g];
    for(int i=t;i<36*32;i+=256) xs[i]=g_x2[g*36*32+i];
    if(t<36){
        ppx[t]=g_ppos1[(g*36+t)*2]; ppy[t]=g_ppos1[(g*36+t)*2+1];
        invd[t]=1.f/fmaxf(g_deg2[g*36+t],1.f);
    }
    for(int i=t;i<901;i+=256) cnt[i]=0;
    __syncthreads();
    float amax=fmaxf(__uint_as_float(g_amax[1]),1e-12f);
    float inv=0.5f/amax;
    for(int i=t;i<ec;i+=256){
        unsigned r=g_el1[g*EPG+i];
        int a=r&255, b=(r>>8)&255;
        float p0=(ppx[a]-ppx[b])*inv+0.5f;
        float p1=(ppy[a]-ppy[b])*inv+0.5f;
        float v0=fminf(fmaxf(p0,0.f),1.f)*4.f;
        float v1=fminf(fmaxf(p1,0.f),1.f)*4.f;
        int i0=(int)fminf(floorf(v0),3.f), i1=(int)fminf(floorf(v1),3.f);
        int base=b*25+i0+5*i1;
        atomicAdd(&cnt[base],1); atomicAdd(&cnt[base+1],1);
        atomicAdd(&cnt[base+5],1); atomicAdd(&cnt[base+6],1);
    }
    __syncthreads();
    {
        int c0=t*4, c1=min(900,c0+4);
        int s=0;
        for(int i=c0;i<c1;i++) s+=cnt[i];
        tsum[t]=s;
        __syncthreads();
        for(int d=1;d<256;d<<=1){
            int v=(t>=d)? tsum[t-d]:0;
            __syncthreads();
            tsum[t]+=v;
            __syncthreads();
        }
        int base=(t==0)?0:tsum[t-1];
        for(int i=c0;i<c1;i++){ int v=cnt[i]; offs[i]=base; base+=v; }
        if(t==255) offs[900]=base;
    }
    __syncthreads();
    for(int i=t;i<900;i+=256) cursor[i]=offs[i];
    __syncthreads();
    for(int i=t;i<ec;i+=256){
        unsigned r=g_el1[g*EPG+i];
        int a=r&255, b=(r>>8)&255;
        float p0=(ppx[a]-ppx[b])*inv+0.5f;
        float p1=(ppy[a]-ppy[b])*inv+0.5f;
        float v0=fminf(fmaxf(p0,0.f),1.f)*4.f;
        float v1=fminf(fmaxf(p1,0.f),1.f)*4.f;
        float b0=fminf(floorf(v0),3.f), b1f=fminf(floorf(v1),3.f);
        int i0=(int)b0, i1=(int)b1f;
        float f0=v0-b0, f1=v1-b1f;
        int base=b*25+i0+5*i1;
        int j;
        j=atomicAdd(&cursor[base],1);   sw_[j]=(1.f-f0)*(1.f-f1); sa_[j]=(unsigned char)a;
        j=atomicAdd(&cursor[base+1],1); sw_[j]=f0*(1.f-f1);       sa_[j]=(unsigned char)a;
        j=atomicAdd(&cursor[base+5],1); sw_[j]=(1.f-f0)*f1;       sa_[j]=(unsigned char)a;
        j=atomicAdd(&cursor[base+6],1); sw_[j]=f0*f1;             sa_[j]=(unsigned char)a;
    }
    __syncthreads();
    for(int b=w;b<900;b+=8){
        int s0=offs[b], s1=offs[b+1];
        float acc=0.f;
        for(int j=s0;j<s1;j++) acc+=sw_[j]*xs[sa_[j]*32+lane];
        acc*=invd[b/25];
        float nxt=__shfl_down_sync(0xffffffffu,acc,1);
        if(!(lane&1)){
            unsigned* po=(unsigned*)&g_acc2h[(size_t)(g*900+b)*32];
            po[lane>>1]=packbf(acc,nxt);
        }
    }
}

// ---------------- bf16 tensor-core conv GEMM ----------------
// out = elu(A@W + X@R + b), deg pre-folded into A. M=128, N=64, K-tile=32.
template<int KK,int FIN>
__global__ __launch_bounds__(256) void k_convB(
    const __nv_bfloat16* __restrict__ A, const __nv_bfloat16* __restrict__ Xh,
    const unsigned* __restrict__ Wp, const float* __restrict__ Bv,
    float* __restrict__ Out)
{
    constexpr int nTA=KK/32, nT=(KK+FIN)/32;
    __shared__ unsigned As2[16][136];
    __shared__ __align__(16) unsigned Ws2[16][72];
    int t=threadIdx.x, lane=t&31, w=t>>5;
    int gid=lane>>2, tig=lane&3;
    int n0=blockIdx.x*128;
    int m0=w*16;
    int r0=n0+m0+gid;
    float C[8][4];
#pragma unroll
    for(int j=0;j<8;j++){ C[j][0]=0.f; C[j][1]=0.f; C[j][2]=0.f; C[j][3]=0.f; }
    int ar=t>>1, half=t&1;
    int wkp=t>>4, wnb=(t&15)*4;
    uint4 pa0,pa1,pw;
    auto loadT=[&](int j){
        const __nv_bfloat16* Ap=(j<nTA)? A+(size_t)(n0+ar)*KK+j*32+half*16
                                       : Xh+(size_t)(n0+ar)*FIN+(j-nTA)*32+half*16;
        pa0=*(const uint4*)Ap;
        pa1=*(const uint4*)(Ap+8);
        pw =*(const uint4*)&Wp[(size_t)(j*16+wkp)*64+wnb];
    };
    loadT(0);
    for(int j=0;j<nT;j++){
        __syncthreads();
        int kb=half*8;
        As2[kb+0][ar]=pa0.x; As2[kb+1][ar]=pa0.y; As2[kb+2][ar]=pa0.z; As2[kb+3][ar]=pa0.w;
        As2[kb+4][ar]=pa1.x; As2[kb+5][ar]=pa1.y; As2[kb+6][ar]=pa1.z; As2[kb+7][ar]=pa1.w;
        *(uint4*)&Ws2[wkp][wnb]=pw;
        __syncthreads();
        if(j+1<nT) loadT(j+1);
#pragma unroll
        for(int s8=0;s8<16;s8+=8){
            unsigned a0=As2[s8+tig  ][m0+gid];
            unsigned a1=As2[s8+tig  ][m0+8+gid];
            unsigned a2=As2[s8+tig+4][m0+gid];
            unsigned a3=As2[s8+tig+4][m0+8+gid];
#pragma unroll
            for(int jj=0;jj<8;jj++){
                unsigned b0=Ws2[s8+tig  ][jj*8+gid];
                unsigned b1=Ws2[s8+tig+4][jj*8+gid];
                mma_bf16(C[jj],a0,a1,a2,a3,b0,b1);
            }
        }
    }
#pragma unroll
    for(int jj=0;jj<8;jj++){
        int c=jj*8+2*tig;
        float bv0=Bv[c], bv1=Bv[c+1];
        float2 o;
        o.x=eluf(C[jj][0]+bv0); o.y=eluf(C[jj][1]+bv1);
        *(float2*)&Out[(size_t)r0*64+c]=o;
        o.x=eluf(C[jj][2]+bv0); o.y=eluf(C[jj][3]+bv1);
        *(float2*)&Out[(size_t)(r0+8)*64+c]=o;
    }
}

// ---------------- pool2 + dedup2 fused (per graph) ----------------
__global__ __launch_bounds__(256) void k_pool2g(){
    int g=blockIdx.x, t=threadIdx.x;
    __shared__ unsigned px[25*64];
    __shared__ float cnt[25], psx[25], psy[25], ppx2[25], ppy2[25], deg3s[25];
    __shared__ unsigned char cl2[36], vld[36];
    __shared__ unsigned bm[20];
    __shared__ int ecnt;
    __shared__ unsigned cmax;
    for(int i=t;i<25*64;i+=256) px[i]=encf(-1e30f);
    if(t<25){ cnt[t]=0.f; psx[t]=0.f; psy[t]=0.f; deg3s[t]=0.f; }
    if(t>=32 && t<52) bm[t-32]=0u;
    if(t==0){ ecnt=0; cmax=0u; }
    __syncthreads();
    if(t<36){
        float qx=g_ppos1[(g*36+t)*2], qy=g_ppos1[(g*36+t)*2+1];
        int c0=min(max((int)floorf(qx/7.f),0),4);
        int c1=min(max((int)floorf(qy/7.f),0),4);
        int c=c1*5+c0;
        cl2[t]=(unsigned char)c;
        unsigned char v=(g_cnt1[g*36+t]>0.f)?1:0;
        vld[t]=v;
        if(v){ atomicAdd(&cnt[c],1.f); atomicAdd(&psx[c],qx); atomicAdd(&psy[c],qy); }
    }
    __syncthreads();
    if(t<25){
        float ic=1.f/fmaxf(cnt[t],1.f);
        ppx2[t]=psx[t]*ic; ppy2[t]=psy[t]*ic;
    }
    __syncthreads();
    for(int i=t;i<36*64;i+=256){
        int s=i>>6, f=i&63;
        if(vld[s]) atomicMax(&px[cl2[s]*64+f], encf(g_x2o[(g*36+s)*64+f]));
    }
    int ec=g_ecnt1[g];
    for(int i=t;i<ec;i+=256){
        unsigned r=g_el1[g*EPG+i];
        int a=cl2[r&255], b=cl2[(r>>8)&255];
        if(a!=b){
            int key=a*25+b;
            unsigned bit=1u<<(key&31);
            if(!(atomicOr(&bm[key>>5],bit)&bit)){
                int idx=atomicAdd(&ecnt,1);
                g_el2[g*EPG+idx]=(unsigned)a|((unsigned)b<<8);
                atomicAdd(&deg3s[b],1.f);
                float c0=fabsf(ppx2[a]-ppx2[b]), c1=fabsf(ppy2[a]-ppy2[b]);
                atomicMax(&cmax,__float_as_uint(fmaxf(c0,c1)));
            }
        }
    }
    __syncthreads();
    for(int i=t;i<25*64;i+=256){
        int s=i>>6, f=i&63;
        float c=cnt[s];
        float v=(c>0.f)? decf(px[i]) : 0.f;
        g_x3[(g*25+s)*64+f]=v;
        g_x3h[(g*25+s)*64+f]=__float2bfloat16(v);
        if(f==0){
            g_cnt2[g*25+s]=c;
            g_ppos2[(g*25+s)*2]=ppx2[s];
            g_ppos2[(g*25+s)*2+1]=ppy2[s];
            g_deg3[g*25+s]=deg3s[s];
        }
    }
    if(t==0){ g_ecnt2[g]=ecnt; redMaxU(&g_amax[2],cmax); }
}

// ---------------- stage-3 CSR gather -> bf16 acc ----------------
__global__ __launch_bounds__(256) void k_gather3(){
    int g=blockIdx.x, t=threadIdx.x, lane=t&31, w=t>>5;
    __shared__ float xs[25*64];
    __shared__ float ppx[25], ppy[25], invd[25];
    __shared__ int cnt[626], offs[626], cursor[625];
    __shared__ int tsum[256];
    __shared__ float sw_[2432];
    __shared__ unsigned char sa_[2432];
    int ec=g_ecnt2[g];
    for(int i=t;i<25*64;i+=256) xs[i]=g_x3[g*25*64+i];
    if(t<25){
        ppx[t]=g_ppos2[(g*25+t)*2]; ppy[t]=g_ppos2[(g*25+t)*2+1];
        invd[t]=1.f/fmaxf(g_deg3[g*25+t],1.f);
    }
    for(int i=t;i<626;i+=256) cnt[i]=0;
    __syncthreads();
    float amax=fmaxf(__uint_as_float(g_amax[2]),1e-12f);
    float inv=0.5f/amax;
    for(int i=t;i<ec;i+=256){
        unsigned r=g_el2[g*EPG+i];
        int a=r&255, b=(r>>8)&255;
        float p0=(ppx[a]-ppx[b])*inv+0.5f;
        float p1=(ppy[a]-ppy[b])*inv+0.5f;
        float v0=fminf(fmaxf(p0,0.f),1.f)*4.f;
        float v1=fminf(fmaxf(p1,0.f),1.f)*4.f;
        int i0=(int)fminf(floorf(v0),3.f), i1=(int)fminf(floorf(v1),3.f);
        int base=b*25+i0+5*i1;
        atomicAdd(&cnt[base],1); atomicAdd(&cnt[base+1],1);
        atomicAdd(&cnt[base+5],1); atomicAdd(&cnt[base+6],1);
    }
    __syncthreads();
    {
        int c0=t*3, c1=min(625,c0+3);
        int s=0;
        for(int i=c0;i<c1;i++) s+=cnt[i];
        tsum[t]=s;
        __syncthreads();
        for(int d=1;d<256;d<<=1){
            int v=(t>=d)? tsum[t-d]:0;
            __syncthreads();
            tsum[t]+=v;
            __syncthreads();
        }
        int base=(t==0)?0:tsum[t-1];
        for(int i=c0;i<c1;i++){ int v=cnt[i]; offs[i]=base; base+=v; }
        if(t==255) offs[625]=base;
    }
    __syncthreads();
    for(int i=t;i<625;i+=256) cursor[i]=offs[i];
    __syncthreads();
    for(int i=t;i<ec;i+=256){
        unsigned r=g_el2[g*EPG+i];
        int a=r&255, b=(r>>8)&255;
        float p0=(ppx[a]-ppx[b])*inv+0.5f;
        float p1=(ppy[a]-ppy[b])*inv+0.5f;
        float v0=fminf(fmaxf(p0,0.f),1.f)*4.f;
        float v1=fminf(fmaxf(p1,0.f),1.f)*4.f;
        float b0=fminf(floorf(v0),3.f), b1f=fminf(floorf(v1),3.f);
        int i0=(int)b0, i1=(int)b1f;
        float f0=v0-b0, f1=v1-b1f;
        int base=b*25+i0+5*i1;
        int j;
        j=atomicAdd(&cursor[base],1);   sw_[j]=(1.f-f0)*(1.f-f1); sa_[j]=(unsigned char)a;
        j=atomicAdd(&cursor[base+1],1); sw_[j]=f0*(1.f-f1);       sa_[j]=(unsigned char)a;
        j=atomicAdd(&cursor[base+5],1); sw_[j]=(1.f-f0)*f1;       sa_[j]=(unsigned char)a;
        j=atomicAdd(&cursor[base+6],1); sw_[j]=f0*f1;             sa_[j]=(unsigned char)a;
    }
    __syncthreads();
    for(int b=w;b<625;b+=8){
        int s0=offs[b], s1=offs[b+1];
        float a0=0.f, a1=0.f;
        for(int j=s0;j<s1;j++){
            float wt=sw_[j]; int a=sa_[j];
            a0+=wt*xs[a*64+lane];
            a1+=wt*xs[a*64+32+lane];
        }
        float iv=invd[b/25];
        a0*=iv; a1*=iv;
        float n0v=__shfl_down_sync(0xffffffffu,a0,1);
        float n1v=__shfl_down_sync(0xffffffffu,a1,1);
        if(!(lane&1)){
            unsigned* po=(unsigned*)&g_acc3h[(size_t)(g*625+b)*64];
            po[lane>>1]=packbf(a0,n0v);
            po[16+(lane>>1)]=packbf(a1,n1v);
        }
    }
}

// ---------------- fused final pool + FC head (per graph) ----------------
__global__ __launch_bounds__(128) void k_headg(const float* __restrict__ fw1,
        const float* __restrict__ fb1, const float* __restrict__ fw2,
        const float* __restrict__ fb2, float* __restrict__ out){
    __shared__ unsigned enc4[4*64];
    __shared__ unsigned any[4];
    __shared__ float in[256];
    __shared__ float h[128];
    __shared__ float lg[10];
    __shared__ float lse;
    int g=blockIdx.x, t=threadIdx.x;
    for(int i=t;i<256;i+=128) enc4[i]=encf(-1e30f);
    if(t<4) any[t]=0u;
    __syncthreads();
    for(int i=t;i<25*64;i+=128){
        int n=i>>6, f=i&63;
        if(g_cnt2[g*25+n]>0.f){
            float qx=g_ppos2[(g*25+n)*2], qy=g_ppos2[(g*25+n)*2+1];
            int c0=min(max((int)floorf(qx/14.f),0),1);
            int c1=min(max((int)floorf(qy/14.f),0),1);
            int cell=c1*2+c0;
            atomicMax(&enc4[cell*64+f], encf(g_x3o[(g*25+n)*64+f]));
            if(f==0) atomicOr(&any[cell],1u);
        }
    }
    __syncthreads();
    for(int i=t;i<256;i+=128)
        in[i]=any[i>>6]? decf(enc4[i]) : 0.f;
    __syncthreads();
    float s=fb1[t];
    const float4* wr=(const float4*)(fw1+(size_t)t*256);
#pragma unroll 8
    for(int i=0;i<64;i++){
        float4 w=wr[i];
        const float4 v=*(const float4*)&in[i*4];
        s+=w.x*v.x+w.y*v.y+w.z*v.z+w.w*v.w;
    }
    h[t]=eluf(s);
    __syncthreads();
    if(t<10){
        float l=fb2[t];
        for(int i=0;i<128;i++) l+=h[i]*fw2[t*128+i];
        lg[t]=l;
    }
    __syncthreads();
    if(t==0){
        float m=lg[0];
        for(int i=1;i<10;i++) m=fmaxf(m,lg[i]);
        float ss=0.f;
        for(int i=0;i<10;i++) ss+=expf(lg[i]-m);
        lse=m+logf(ss);
    }
    __syncthreads();
    if(t<10) out[g*10+t]=lg[t]-lse;
}

// ---------------- launch ----------------
extern "C" void kernel_launch(void* const* d_in, const int* in_sizes, int n_in,
                              void* d_out, int out_size){
    const float* x   =(const float*)d_in[0];
    const float* pos =(const float*)d_in[1];
    const int*   src =(const int*)  d_in[2];
    const int*   dst =(const int*)  d_in[3];
    const float* W1  =(const float*)d_in[4];
    const float* r1  =(const float*)d_in[5];
    const float* b1  =(const float*)d_in[6];
    const float* W2  =(const float*)d_in[7];
    const float* r2  =(const float*)d_in[8];
    const float* b2  =(const float*)d_in[9];
    const float* W3  =(const float*)d_in[10];
    const float* r3  =(const float*)d_in[11];
    const float* b3  =(const float*)d_in[12];
    const float* fw1 =(const float*)d_in[13];
    const float* fb1 =(const float*)d_in[14];
    const float* fw2 =(const float*)d_in[15];
    const float* fb2 =(const float*)d_in[16];
    float* out=(float*)d_out;

    __nv_bfloat16 *pA2h,*pX2h,*pA3h,*pX3h;
    unsigned *pWp2,*pWp3;
    float *pX2o,*pX3o;
    cudaGetSymbolAddress((void**)&pA2h, g_acc2h);
    cudaGetSymbolAddress((void**)&pX2h, g_x2h);
    cudaGetSymbolAddress((void**)&pA3h, g_acc3h);
    cudaGetSymbolAddress((void**)&pX3h, g_x3h);
    cudaGetSymbolAddress((void**)&pWp2, g_Wp2);
    cudaGetSymbolAddress((void**)&pWp3, g_Wp3);
    cudaGetSymbolAddress((void**)&pX2o, g_x2o);
    cudaGetSymbolAddress((void**)&pX3o, g_x3o);

    k_reset0<<<1,32>>>();
    k_prepW<<<(416*64+832*64+255)/256,256>>>(W2,r2,W3,r3);
    k_amax0g<<<BB,256>>>(pos,src,dst);
    k_stage1<<<BB,256>>>(x,pos,src,dst,W1,r1,b1);
    k_gather2<<<BB,256>>>();
    k_convB<800,32><<<S1C/128,256>>>(pA2h,pX2h,pWp2,b2,pX2o);
    k_pool2g<<<BB,256>>>();
    k_gather3<<<BB,256>>>();
    k_convB<1600,64><<<S2C/128,256>>>(pA3h,pX3h,pWp3,b3,pX3o);
    k_headg<<<BB,128>>>(fw1,fb1,fw2,fb2,out);
}